// round 10
// baseline (speedup 1.0000x reference)
#include <cuda_runtime.h>
#include <cuda_bf16.h>
#include <math.h>
#include <stdint.h>

// Problem constants
#define B_  4096
#define T_  200
#define E_  64
#define A1_ 64
#define A2_ 32
#define M1_ 256
#define M2_ 128
#define GRID_MAIN 296   // 2 CTAs per SM x 148 SMs

// -------- device scratch (no allocations allowed) --------
__device__ float g_inter[B_ * 64]; // interest vectors

// ---- tf32 helpers ----
__device__ __forceinline__ unsigned int f2tf(float f) {
    unsigned int r;
    asm("cvt.rna.tf32.f32 %0, %1;" : "=r"(r) : "f"(f));
    return r;
}
__device__ __forceinline__ void split_tf32(float x, unsigned int& hi, unsigned int& lo) {
    hi = f2tf(x);
    lo = f2tf(x - __uint_as_float(hi));
}
__device__ __forceinline__ void mma_tf32(
    float& c0, float& c1, float& c2, float& c3,
    unsigned int a0, unsigned int a1, unsigned int a2, unsigned int a3,
    unsigned int b0, unsigned int b1) {
    asm("mma.sync.aligned.m16n8k8.row.col.f32.tf32.tf32.f32 "
        "{%0,%1,%2,%3},{%4,%5,%6,%7},{%8,%9},{%0,%1,%2,%3};"
        : "+f"(c0), "+f"(c1), "+f"(c2), "+f"(c3)
        : "r"(a0), "r"(a1), "r"(a2), "r"(a3), "r"(b0), "r"(b1));
}
// ---- cp.async helpers ----
__device__ __forceinline__ void cp_async16(unsigned int dst, const void* src) {
    asm volatile("cp.async.ca.shared.global [%0], [%1], 16;" :: "r"(dst), "l"(src) : "memory");
}
__device__ __forceinline__ unsigned int smem_u32(const void* p) {
    return (unsigned int)__cvta_generic_to_shared(p);
}
#define CP_COMMIT() asm volatile("cp.async.commit_group;" ::: "memory")
#define CP_WAIT0()  asm volatile("cp.async.wait_group 0;" ::: "memory")

// ============================================================
// main kernel: PERSISTENT, 296 CTAs x 512 threads, 2 CTAs/SM.
// Gather-first issue order; next-batch QV/mask prefetched into regs.
// ============================================================
#define PH 68
// smem layout (float offsets)
#define OFF_HIST  0        // 208*68 = 14144
#define OFF_WCU   14144    // 4352
#define OFF_W2U   18496    // 2304
#define OFF_QV    20800    // 64
#define OFF_QB    20864    // 64
#define OFF_AB2   20928    // 32
#define OFF_AOW   20960    // 32
#define OFF_SC    20992    // 208
#define OFF_MSK   21200    // 208 (int view)
#define OFF_WRED  21408    // 32
#define OFF_RED   21440    // 512
#define OFF_WHPB  21952    // 4096 (bf16x2 packed Wh,Wp)
#define OFF_WQB   26048    // 2048 (bf16 Wq)
#define SMEM_B_FLOATS 28096
#define SMEM_B_BYTES  (SMEM_B_FLOATS * 4)

__global__ __launch_bounds__(512, 2) void din_main(
    const int* __restrict__ hist_id,
    const int* __restrict__ mask,        // bool promoted to 4-byte; test != 0
    const float* __restrict__ table,
    const int* __restrict__ target,
    const float* __restrict__ aw1,
    const float* __restrict__ ab1,
    const float* __restrict__ aw2,
    const float* __restrict__ ab2,
    const float* __restrict__ aow,
    const float* __restrict__ aob) {
    extern __shared__ float sm[];
    unsigned int* smu = (unsigned int*)sm;
    int* smi = (int*)sm;
    __nv_bfloat162* whpb = (__nv_bfloat162*)(smu + OFF_WHPB);
    __nv_bfloat16*  wqb  = (__nv_bfloat16*)(smu + OFF_WQB);
    const int tid = threadIdx.x;
    const int w   = tid >> 5;
    const int l   = tid & 31;
    const int l4  = l >> 2;   // 0..7
    const int lm  = l & 3;    // 0..3

    // ---- loop-invariant staging (once per CTA) ----
    if (tid < 32)        sm[OFF_AB2 + tid]      = ab2[tid];
    else if (tid < 64)   sm[OFF_AOW + tid - 32] = aow[tid - 32];
    for (int idx = tid; idx < 64 * 32; idx += 512) {
        int n = idx & 31, k = idx >> 5;
        smu[OFF_W2U + k * 36 + n] = f2tf(aw2[k * 32 + n]);
    }
    for (int idx = tid; idx < 64 * 64; idx += 512) {
        int j = idx & 63, k = idx >> 6;
        float a = aw1[k * 64 + j];
        float bb = aw1[(64 + k) * 64 + j];
        float c = aw1[(128 + k) * 64 + j];
        float d = aw1[(192 + k) * 64 + j];
        __nv_bfloat162 v;
        v.x = __float2bfloat16(a + c);   // Wh
        v.y = __float2bfloat16(d);       // Wp
        whpb[idx] = v;
        wqb[idx] = __float2bfloat16(bb - c);
    }
    // ---- first-batch QV/mask staging ----
    {
        int b0i = blockIdx.x;
        if (tid < 64)
            sm[OFF_QV + tid] = table[(size_t)target[b0i] * 64 + tid];
        else if (tid < 264)
            smi[OFF_MSK + tid - 64] = mask[b0i * T_ + tid - 64];
    }
    const float aob0 = aob[0];
    const float ab1v = (tid < 64) ? ab1[tid] : 0.f;

    for (int b = blockIdx.x; b < B_; b += GRID_MAIN) {
        __syncthreads();   // B0: prior iter done; QV/MSK staged

        // --- gather history embeddings FIRST (long-latency LDGs in flight) ---
        {
            const float4* tab4 = (const float4*)table;
            float4* hist4 = (float4*)(sm + OFF_HIST);
            for (int idx = tid; idx < T_ * 16; idx += 512) {
                int t = idx >> 4, v = idx & 15;
                hist4[t * 17 + v] = tab4[(size_t)hist_id[b * T_ + t] * 16 + v];
            }
            for (int idx = tid; idx < 8 * 17; idx += 512) {
                int t = 200 + idx / 17, v = idx % 17;
                hist4[t * 17 + v] = make_float4(0.f, 0.f, 0.f, 0.f);
            }
        }
        // --- qb partials: all 512 threads, LDS-only Wq ---
        {
            int n = tid & 63, kc = tid >> 6;
            float acc = 0.f;
#pragma unroll
            for (int i = 0; i < 8; ++i) {
                int k = kc * 8 + i;
                acc = fmaf(sm[OFF_QV + k], __bfloat162float(wqb[k * 64 + n]), acc);
            }
            sm[OFF_RED + kc * 64 + n] = acc;
        }
        __syncthreads();   // B1.5: partials ready
        if (tid < 64) {
            float acc = ab1v;
#pragma unroll
            for (int kc = 0; kc < 8; ++kc) acc += sm[OFF_RED + kc * 64 + tid];
            sm[OFF_QB + tid] = acc;
        }
        // --- fold Wc[k][n] = Wh + q[k]*Wp, store tf32 bits ---
        for (int idx = tid; idx < 64 * 64; idx += 512) {
            int n = idx & 63, k = idx >> 6;
            __nv_bfloat162 hp = whpb[idx];
            smu[OFF_WCU + k * PH + n] =
                f2tf(fmaf(sm[OFF_QV + k], __bfloat162float(hp.y),
                          __bfloat162float(hp.x)));
        }
        __syncthreads();   // B2: all operands staged

        // --- prefetch next batch QV/mask into registers (hidden under mma) ---
        const int nb = b + GRID_MAIN;
        float pf_qv = 0.f; int pf_mk = 0;
        if (nb < B_) {
            if (tid < 64)        pf_qv = table[(size_t)target[nb] * 64 + tid];
            else if (tid < 264)  pf_mk = mask[nb * T_ + tid - 64];
        }

        // ====== fused attention MLP: warps 0..12 own rows [16w, 16w+16) ======
        if (w < 13) {
            const int mt = w;

            unsigned int au[32];
            {
                const float* abase = sm + OFF_HIST + (mt * 16 + l4) * PH + lm;
#pragma unroll
                for (int k = 0; k < 8; ++k) {
                    au[4 * k + 0] = f2tf(abase[k * 8]);
                    au[4 * k + 1] = f2tf(abase[8 * PH + k * 8]);
                    au[4 * k + 2] = f2tf(abase[k * 8 + 4]);
                    au[4 * k + 3] = f2tf(abase[8 * PH + k * 8 + 4]);
                }
            }

            float d0[4], d1[4], d2[4], d3[4];
#pragma unroll
            for (int nt2 = 0; nt2 < 4; ++nt2) {
                float bb0 = sm[OFF_AB2 + nt2 * 8 + 2 * lm];
                float bb1 = sm[OFF_AB2 + nt2 * 8 + 2 * lm + 1];
                d0[nt2] = bb0; d1[nt2] = bb1; d2[nt2] = bb0; d3[nt2] = bb1;
            }

            const unsigned int* wc_col = smu + OFF_WCU + lm * PH;
            const unsigned int* w2_col = smu + OFF_W2U + lm * 36 + l4;

            for (int kk = 0; kk < 8; ++kk) {
                float c0 = sm[OFF_QB + kk * 8 + 2 * lm];
                float c1 = sm[OFF_QB + kk * 8 + 2 * lm + 1];
                float c2 = c0, c3 = c1;
                const unsigned int* wcb = wc_col + kk * 8 + l4;
#pragma unroll
                for (int k = 0; k < 8; ++k) {
                    unsigned int b0v = wcb[k * 8 * PH];
                    unsigned int b1v = wcb[k * 8 * PH + 4 * PH];
                    mma_tf32(c0, c1, c2, c3,
                             au[4 * k], au[4 * k + 1], au[4 * k + 2], au[4 * k + 3],
                             b0v, b1v);
                }
                c0 = fmaxf(c0, 0.f); c1 = fmaxf(c1, 0.f);
                c2 = fmaxf(c2, 0.f); c3 = fmaxf(c3, 0.f);

                int src1 = (l & ~3) + (lm >> 1);
                int src2 = src1 + 2;
                float v0a = __shfl_sync(0xffffffffu, c0, src1);
                float v1a = __shfl_sync(0xffffffffu, c1, src1);
                float v2a = __shfl_sync(0xffffffffu, c2, src1);
                float v3a = __shfl_sync(0xffffffffu, c3, src1);
                float v0b = __shfl_sync(0xffffffffu, c0, src2);
                float v1b = __shfl_sync(0xffffffffu, c1, src2);
                float v2b = __shfl_sync(0xffffffffu, c2, src2);
                float v3b = __shfl_sync(0xffffffffu, c3, src2);
                bool hi = (lm & 1);
                unsigned int a0 = f2tf(hi ? v1a : v0a);
                unsigned int a1 = f2tf(hi ? v3a : v2a);
                unsigned int a2 = f2tf(hi ? v1b : v0b);
                unsigned int a3 = f2tf(hi ? v3b : v2b);

                const unsigned int* w2b = w2_col + kk * 8 * 36;
#pragma unroll
                for (int nt2 = 0; nt2 < 4; ++nt2) {
                    unsigned int b0v = w2b[nt2 * 8];
                    unsigned int b1v = w2b[nt2 * 8 + 4 * 36];
                    mma_tf32(d0[nt2], d1[nt2], d2[nt2], d3[nt2],
                             a0, a1, a2, a3, b0v, b1v);
                }
            }

            float p01 = 0.f, p23 = 0.f;
#pragma unroll
            for (int nt2 = 0; nt2 < 4; ++nt2) {
                float w0 = sm[OFF_AOW + nt2 * 8 + 2 * lm];
                float w1 = sm[OFF_AOW + nt2 * 8 + 2 * lm + 1];
                p01 = fmaf(fmaxf(d0[nt2], 0.f), w0, fmaf(fmaxf(d1[nt2], 0.f), w1, p01));
                p23 = fmaf(fmaxf(d2[nt2], 0.f), w0, fmaf(fmaxf(d3[nt2], 0.f), w1, p23));
            }
            p01 += __shfl_xor_sync(0xffffffffu, p01, 1);
            p01 += __shfl_xor_sync(0xffffffffu, p01, 2);
            p23 += __shfl_xor_sync(0xffffffffu, p23, 1);
            p23 += __shfl_xor_sync(0xffffffffu, p23, 2);
            if (lm == 0) {
                int r0 = mt * 16 + l4;
                int r1 = r0 + 8;
                if (r0 < T_)
                    sm[OFF_SC + r0] = (smi[OFF_MSK + r0] != 0) ? p01 + aob0 : -1e9f;
                if (r1 < T_)
                    sm[OFF_SC + r1] = (smi[OFF_MSK + r1] != 0) ? p23 + aob0 : -1e9f;
            }
        }
        __syncthreads();   // B3: scores ready

        // ---- softmax ----
        float v = (tid < T_) ? sm[OFF_SC + tid] : -1e30f;
        float m = v;
        m = fmaxf(m, __shfl_xor_sync(0xffffffffu, m, 16));
        m = fmaxf(m, __shfl_xor_sync(0xffffffffu, m, 8));
        m = fmaxf(m, __shfl_xor_sync(0xffffffffu, m, 4));
        m = fmaxf(m, __shfl_xor_sync(0xffffffffu, m, 2));
        m = fmaxf(m, __shfl_xor_sync(0xffffffffu, m, 1));
        if (l == 0) sm[OFF_WRED + w] = m;
        __syncthreads();   // B4
        float gm = sm[OFF_WRED + 0];
#pragma unroll
        for (int i = 1; i < 16; ++i) gm = fmaxf(gm, sm[OFF_WRED + i]);
        float e = (tid < T_) ? __expf(v - gm) : 0.f;
        if (tid < T_) sm[OFF_SC + tid] = e;
        float s = e;
        s += __shfl_xor_sync(0xffffffffu, s, 16);
        s += __shfl_xor_sync(0xffffffffu, s, 8);
        s += __shfl_xor_sync(0xffffffffu, s, 4);
        s += __shfl_xor_sync(0xffffffffu, s, 2);
        s += __shfl_xor_sync(0xffffffffu, s, 1);
        if (l == 0) sm[OFF_WRED + 16 + w] = s;
        __syncthreads();   // B5

        // ---- interest (normalization folded in) ----
        {
            float ss = sm[OFF_WRED + 16];
#pragma unroll
            for (int i = 1; i < 16; ++i) ss += sm[OFF_WRED + 16 + i];
            float inv = 1.f / ss;
            int j = tid & 63, g = tid >> 6;
            float acc = 0.f;
            for (int t = g * 25; t < (g + 1) * 25; ++t)
                acc = fmaf(sm[OFF_SC + t], sm[OFF_HIST + t * PH + j], acc);
            sm[OFF_RED + g * 64 + j] = acc * inv;
        }
        __syncthreads();   // B6
        if (tid < 64) {
            float iv = 0.f;
#pragma unroll
            for (int g = 0; g < 8; ++g) iv += sm[OFF_RED + g * 64 + tid];
            g_inter[b * 64 + tid] = iv;
        }
        // ---- store prefetched next-batch QV/mask (B0 next iter publishes) ----
        if (nb < B_) {
            if (tid < 64)        sm[OFF_QV + tid] = pf_qv;
            else if (tid < 264)  smi[OFF_MSK + tid - 64] = pf_mk;
        }
    }
}

// ============================================================
// final MLP v5: tf32x2, 16 rows/CTA, grid 256 (all SMs), 256 threads,
// unified 12-chunk cp.async double-buffered weight pipeline.
// ============================================================
#define DR  16
#define FPX 136
#define FPW 264
#define FX    0        // 16*136 = 2176
#define FG1   2176     // 16*264 = 4224 -> 6400
#define FWT0  6400     // 8448 -> 14848
#define FWT1  14848    // 8448 -> 23296
#define FMB1  23296    // 256
#define FMB2  23552    // 128
#define FOW   23680    // 128
#define FRED  23808    // 128
#define FTGT  23936    // 16 (int view)
#define SMEM_F_FLOATS 23952
#define SMEM_F_BYTES  (SMEM_F_FLOATS * 4)

__global__ __launch_bounds__(256, 2) void din_final(
    const int* __restrict__ target,
    const float* __restrict__ table,
    const float* __restrict__ mw1, const float* __restrict__ mb1,
    const float* __restrict__ mw2, const float* __restrict__ mb2,
    const float* __restrict__ ow,  const float* __restrict__ ob,
    float* __restrict__ out) {
    extern __shared__ float sm[];
    int* smi = (int*)sm;
    const int tid = threadIdx.x;
    const int w   = tid >> 5;   // 0..7
    const int l   = tid & 31;
    const int l4  = l >> 2;
    const int lm  = l & 3;
    const int b0  = blockIdx.x * DR;

    if (tid < DR) smi[FTGT + tid] = target[b0 + tid];
    sm[FMB1 + tid] = mb1[tid];
    if (tid < 128) { sm[FMB2 + tid] = mb2[tid]; sm[FOW + tid] = ow[tid]; }
    __syncthreads();

    // ---- X = concat(item, interest), fp32 ----
    {
        const float4* tab4 = (const float4*)table;
        const float4* int4p = (const float4*)g_inter;
        for (int idx = tid; idx < DR * 32; idx += 256) {
            int rr = idx >> 5, v = idx & 31;
            float4 x = (v < 16)
                ? tab4[(size_t)smi[FTGT + rr] * 16 + v]
                : int4p[(size_t)(b0 + rr) * 16 + (v - 16)];
            *(float4*)(sm + FX + rr * FPX + v * 4) = x;
        }
    }

    // ---- issue chunk 0 (mw1 rows 0..32) into FWT0 ----
    {
        const float4* src = (const float4*)mw1;
        float* dst = sm + FWT0;
        for (int idx = tid; idx < 2048; idx += 256) {
            int r = idx >> 6, v = idx & 63;
            cp_async16(smem_u32(dst + r * FPW + v * 4), src + idx);
        }
        CP_COMMIT();
    }

    const int n0w  = w * 32;
    const int n0w2 = w * 16;
    float acc1[16], acc2[8];

    for (int c = 0; c < 12; ++c) {
        CP_WAIT0();
        __syncthreads();   // chunk c visible; prior compute done (buffer reuse safe)

        // issue chunk c+1 into the other buffer (overlaps compute of chunk c)
        if (c < 11) {
            int nc = c + 1;
            float* dst = sm + ((nc & 1) ? FWT1 : FWT0);
            if (nc < 4) {
                const float4* src = (const float4*)(mw1 + nc * 32 * 256);
                for (int idx = tid; idx < 2048; idx += 256) {
                    int r = idx >> 6, v = idx & 63;
                    cp_async16(smem_u32(dst + r * FPW + v * 4), src + idx);
                }
            } else {
                const float4* src = (const float4*)(mw2 + (nc - 4) * 32 * 128);
                for (int idx = tid; idx < 1024; idx += 256) {
                    int r = idx >> 5, v = idx & 31;
                    cp_async16(smem_u32(dst + r * FPX + v * 4), src + idx);
                }
            }
            CP_COMMIT();
        }

        const float* wt = sm + ((c & 1) ? FWT1 : FWT0);

        if (c == 0) {
#pragma unroll
            for (int nt = 0; nt < 4; ++nt) {
                float bb0 = sm[FMB1 + n0w + nt * 8 + 2 * lm];
                float bb1 = sm[FMB1 + n0w + nt * 8 + 2 * lm + 1];
                acc1[nt * 4 + 0] = bb0; acc1[nt * 4 + 1] = bb1;
                acc1[nt * 4 + 2] = bb0; acc1[nt * 4 + 3] = bb1;
            }
        }
        if (c == 4) {
#pragma unroll
            for (int nt = 0; nt < 2; ++nt) {
                float bb0 = sm[FMB2 + n0w2 + nt * 8 + 2 * lm];
                float bb1 = sm[FMB2 + n0w2 + nt * 8 + 2 * lm + 1];
                acc2[nt * 4 + 0] = bb0; acc2[nt * 4 + 1] = bb1;
                acc2[nt * 4 + 2] = bb0; acc2[nt * 4 + 3] = bb1;
            }
        }

        if (c < 4) {
            // ---- stage 1: X chunk [32c..32c+32) @ mw1 chunk ----
#pragma unroll
            for (int s = 0; s < 4; ++s) {
                const float* ab = sm + FX + l4 * FPX + c * 32 + s * 8 + lm;
                unsigned int ah0, al0, ah1, al1, ah2, al2, ah3, al3;
                split_tf32(ab[0],           ah0, al0);
                split_tf32(ab[8 * FPX],     ah1, al1);
                split_tf32(ab[4],           ah2, al2);
                split_tf32(ab[8 * FPX + 4], ah3, al3);
#pragma unroll
                for (int nt = 0; nt < 4; ++nt) {
                    float b0f = wt[(s * 8 + lm) * FPW + n0w + nt * 8 + l4];
                    float b1f = wt[(s * 8 + lm + 4) * FPW + n0w + nt * 8 + l4];
                    unsigned int b0h, b0l, b1h, b1l;
                    split_tf32(b0f, b0h, b0l);
                    split_tf32(b1f, b1h, b1l);
                    int base = nt * 4;
                    mma_tf32(acc1[base + 0], acc1[base + 1], acc1[base + 2], acc1[base + 3],
                             ah0, ah1, ah2, ah3, b0h, b1h);
                    mma_tf32(acc1[base + 0], acc1[base + 1], acc1[base + 2], acc1[base + 3],
                             al0, al1, al2, al3, b0h, b1h);
                    mma_tf32(acc1[base + 0], acc1[base + 1], acc1[base + 2], acc1[base + 3],
                             ah0, ah1, ah2, ah3, b0l, b1l);
                }
            }
            if (c == 3) {
                // G1 = relu(acc1), fp32 (consumed after next chunk's barrier)
#pragma unroll
                for (int nt = 0; nt < 4; ++nt) {
                    int base = nt * 4;
                    int col = n0w + nt * 8 + 2 * lm;
                    *(float2*)(sm + FG1 + l4 * FPW + col) =
                        make_float2(fmaxf(acc1[base + 0], 0.f), fmaxf(acc1[base + 1], 0.f));
                    *(float2*)(sm + FG1 + (l4 + 8) * FPW + col) =
                        make_float2(fmaxf(acc1[base + 2], 0.f), fmaxf(acc1[base + 3], 0.f));
                }
            }
        } else {
            // ---- stage 2: G1 chunk [32(c-4)..) @ mw2 chunk ----
            int ck = c - 4;
#pragma unroll
            for (int s = 0; s < 4; ++s) {
                const float* ab = sm + FG1 + l4 * FPW + ck * 32 + s * 8 + lm;
                unsigned int ah0, al0, ah1, al1, ah2, al2, ah3, al3;
                split_tf32(ab[0],           ah0, al0);
                split_tf32(ab[8 * FPW],     ah1, al1);
                split_tf32(ab[4],           ah2, al2);
                split_tf32(ab[8 * FPW + 4], ah3, al3);
#pragma unroll
                for (int nt = 0; nt < 2; ++nt) {
                    float b0f = wt[(s * 8 + lm) * FPX + n0w2 + nt * 8 + l4];
                    float b1f = wt[(s * 8 + lm + 4) * FPX + n0w2 + nt * 8 + l4];
                    unsigned int b0h, b0l, b1h, b1l;
                    split_tf32(b0f, b0h, b0l);
                    split_tf32(b1f, b1h, b1l);
                    int base = nt * 4;
                    mma_tf32(acc2[base + 0], acc2[base + 1], acc2[base + 2], acc2[base + 3],
                             ah0, ah1, ah2, ah3, b0h, b1h);
                    mma_tf32(acc2[base + 0], acc2[base + 1], acc2[base + 2], acc2[base + 3],
                             al0, al1, al2, al3, b0h, b1h);
                    mma_tf32(acc2[base + 0], acc2[base + 1], acc2[base + 2], acc2[base + 3],
                             ah0, ah1, ah2, ah3, b0l, b1l);
                }
            }
        }
    }

    // ---- stage 3: out = relu(acc2) @ ow + ob ----
    float pA = 0.f, pB = 0.f;
#pragma unroll
    for (int nt = 0; nt < 2; ++nt) {
        int base = nt * 4;
        float w0 = sm[FOW + n0w2 + nt * 8 + 2 * lm];
        float w1 = sm[FOW + n0w2 + nt * 8 + 2 * lm + 1];
        pA = fmaf(fmaxf(acc2[base + 0], 0.f), w0,
             fmaf(fmaxf(acc2[base + 1], 0.f), w1, pA));
        pB = fmaf(fmaxf(acc2[base + 2], 0.f), w0,
             fmaf(fmaxf(acc2[base + 3], 0.f), w1, pB));
    }
    pA += __shfl_xor_sync(0xffffffffu, pA, 1);
    pA += __shfl_xor_sync(0xffffffffu, pA, 2);
    pB += __shfl_xor_sync(0xffffffffu, pB, 1);
    pB += __shfl_xor_sync(0xffffffffu, pB, 2);
    if (lm == 0) {
        sm[FRED + w * 16 + l4]     = pA;
        sm[FRED + w * 16 + l4 + 8] = pB;
    }
    __syncthreads();
    if (tid < DR) {
        float p = ob[0];
#pragma unroll
        for (int w8 = 0; w8 < 8; ++w8) p += sm[FRED + w8 * 16 + tid];
        out[b0 + tid] = p;
    }
}

// ============================================================
// launch
// ============================================================
extern "C" void kernel_launch(void* const* d_in, const int* in_sizes, int n_in,
                              void* d_out, int out_size) {
    const int*   target  = (const int*)d_in[0];
    const int*   hist_id = (const int*)d_in[1];
    const int*   mask    = (const int*)d_in[2];     // bool promoted; test != 0
    const float* table   = (const float*)d_in[3];
    const float* aw1     = (const float*)d_in[4];
    const float* ab1     = (const float*)d_in[5];
    const float* aw2     = (const float*)d_in[6];
    const float* ab2     = (const float*)d_in[7];
    const float* aow     = (const float*)d_in[8];
    const float* aob     = (const float*)d_in[9];
    const float* mw1     = (const float*)d_in[10];
    const float* mb1     = (const float*)d_in[11];
    const float* mw2     = (const float*)d_in[12];
    const float* mb2     = (const float*)d_in[13];
    const float* ow      = (const float*)d_in[14];
    const float* ob      = (const float*)d_in[15];
    float* out = (float*)d_out;

    cudaFuncSetAttribute(din_main, cudaFuncAttributeMaxDynamicSharedMemorySize, SMEM_B_BYTES);
    cudaFuncSetAttribute(din_final, cudaFuncAttributeMaxDynamicSharedMemorySize, SMEM_F_BYTES);

    din_main<<<GRID_MAIN, 512, SMEM_B_BYTES>>>(hist_id, mask, table, target, aw1,
                                               ab1, aw2, ab2, aow, aob);
    din_final<<<B_ / DR, 256, SMEM_F_BYTES>>>(target, table, mw1, mb1,
                                              mw2, mb2, ow, ob, out);
}

// round 11
// speedup vs baseline: 1.0347x; 1.0347x over previous
#include <cuda_runtime.h>
#include <cuda_bf16.h>
#include <math.h>
#include <stdint.h>

// Problem constants
#define B_  4096
#define T_  200
#define E_  64
#define A1_ 64
#define A2_ 32
#define M1_ 256
#define M2_ 128
#define GRID_MAIN 296   // 2 CTAs per SM x 148 SMs

// -------- device scratch (no allocations allowed) --------
__device__ float g_inter[B_ * 64]; // interest vectors

// ---- tf32 helpers ----
__device__ __forceinline__ unsigned int f2tf(float f) {
    unsigned int r;
    asm("cvt.rna.tf32.f32 %0, %1;" : "=r"(r) : "f"(f));
    return r;
}
__device__ __forceinline__ void split_tf32(float x, unsigned int& hi, unsigned int& lo) {
    hi = f2tf(x);
    lo = f2tf(x - __uint_as_float(hi));
}
__device__ __forceinline__ void mma_tf32(
    float& c0, float& c1, float& c2, float& c3,
    unsigned int a0, unsigned int a1, unsigned int a2, unsigned int a3,
    unsigned int b0, unsigned int b1) {
    asm("mma.sync.aligned.m16n8k8.row.col.f32.tf32.tf32.f32 "
        "{%0,%1,%2,%3},{%4,%5,%6,%7},{%8,%9},{%0,%1,%2,%3};"
        : "+f"(c0), "+f"(c1), "+f"(c2), "+f"(c3)
        : "r"(a0), "r"(a1), "r"(a2), "r"(a3), "r"(b0), "r"(b1));
}
// ---- cp.async helpers ----
__device__ __forceinline__ void cp_async16(unsigned int dst, const void* src) {
    asm volatile("cp.async.ca.shared.global [%0], [%1], 16;" :: "r"(dst), "l"(src) : "memory");
}
__device__ __forceinline__ unsigned int smem_u32(const void* p) {
    return (unsigned int)__cvta_generic_to_shared(p);
}
#define CP_COMMIT() asm volatile("cp.async.commit_group;" ::: "memory")
#define CP_WAIT0()  asm volatile("cp.async.wait_group 0;" ::: "memory")

// ============================================================
// main kernel: PERSISTENT, 296 CTAs x 512 threads, 2 CTAs/SM.
// R8 structure + register-free cp.async hist gather overlapped
// with qb/fold compute (issued after B1, waited at B2).
// ============================================================
#define PH 68
// smem layout (float offsets)
#define OFF_HIST  0        // 208*68 = 14144
#define OFF_WCU   14144    // 4352
#define OFF_W2U   18496    // 2304
#define OFF_QV    20800    // 64
#define OFF_QB    20864    // 64
#define OFF_AB2   20928    // 32
#define OFF_AOW   20960    // 32
#define OFF_SC    20992    // 208
#define OFF_MSK   21200    // 208 (int view)
#define OFF_WRED  21408    // 32
#define OFF_RED   21440    // 512
#define OFF_WHPB  21952    // 4096 (bf16x2 packed Wh,Wp)
#define OFF_WQB   26048    // 2048 (bf16 Wq)
#define SMEM_B_FLOATS 28096
#define SMEM_B_BYTES  (SMEM_B_FLOATS * 4)

__global__ __launch_bounds__(512, 2) void din_main(
    const int* __restrict__ hist_id,
    const int* __restrict__ mask,        // bool promoted to 4-byte; test != 0
    const float* __restrict__ table,
    const int* __restrict__ target,
    const float* __restrict__ aw1,
    const float* __restrict__ ab1,
    const float* __restrict__ aw2,
    const float* __restrict__ ab2,
    const float* __restrict__ aow,
    const float* __restrict__ aob) {
    extern __shared__ float sm[];
    unsigned int* smu = (unsigned int*)sm;
    int* smi = (int*)sm;
    __nv_bfloat162* whpb = (__nv_bfloat162*)(smu + OFF_WHPB);
    __nv_bfloat16*  wqb  = (__nv_bfloat16*)(smu + OFF_WQB);
    const int tid = threadIdx.x;
    const int w   = tid >> 5;
    const int l   = tid & 31;
    const int l4  = l >> 2;   // 0..7
    const int lm  = l & 3;    // 0..3

    // ---- loop-invariant staging (once per CTA) ----
    if (tid < 32)        sm[OFF_AB2 + tid]      = ab2[tid];
    else if (tid < 64)   sm[OFF_AOW + tid - 32] = aow[tid - 32];
    for (int idx = tid; idx < 64 * 32; idx += 512) {
        int n = idx & 31, k = idx >> 5;
        smu[OFF_W2U + k * 36 + n] = f2tf(aw2[k * 32 + n]);
    }
    for (int idx = tid; idx < 64 * 64; idx += 512) {
        int j = idx & 63, k = idx >> 6;
        float a = aw1[k * 64 + j];
        float bb = aw1[(64 + k) * 64 + j];
        float c = aw1[(128 + k) * 64 + j];
        float d = aw1[(192 + k) * 64 + j];
        __nv_bfloat162 v;
        v.x = __float2bfloat16(a + c);   // Wh
        v.y = __float2bfloat16(d);       // Wp
        whpb[idx] = v;
        wqb[idx] = __float2bfloat16(bb - c);
    }
    // zero-pad HIST rows 200..207 ONCE (never overwritten afterwards)
    {
        float4* hist4 = (float4*)(sm + OFF_HIST);
        for (int idx = tid; idx < 8 * 17; idx += 512) {
            int t = 200 + idx / 17, v = idx % 17;
            hist4[t * 17 + v] = make_float4(0.f, 0.f, 0.f, 0.f);
        }
    }
    const float aob0 = aob[0];
    const float ab1v = (tid < 64) ? ab1[tid] : 0.f;

    for (int b = blockIdx.x; b < B_; b += GRID_MAIN) {
        __syncthreads();   // B0: prior iteration fully done

        // --- per-batch staging: item embedding + mask ---
        if (tid < 64)
            sm[OFF_QV + tid] = table[(size_t)target[b] * 64 + tid];
        else if (tid < 264)
            smi[OFF_MSK + tid - 64] = mask[b * T_ + tid - 64];
        __syncthreads();   // B1: QV ready; prior-iter HIST reads done

        // --- issue hist gather via cp.async (register-free), overlap below ---
        {
            const float4* tab4 = (const float4*)table;
            float* histb = sm + OFF_HIST;
            for (int idx = tid; idx < T_ * 16; idx += 512) {
                int t = idx >> 4, v = idx & 15;
                cp_async16(smem_u32(histb + t * PH + v * 4),
                           tab4 + (size_t)hist_id[b * T_ + t] * 16 + v);
            }
            CP_COMMIT();
        }
        // --- qb partials: all 512 threads, LDS-only Wq (overlaps gather) ---
        {
            int n = tid & 63, kc = tid >> 6;
            float acc = 0.f;
#pragma unroll
            for (int i = 0; i < 8; ++i) {
                int k = kc * 8 + i;
                acc = fmaf(sm[OFF_QV + k], __bfloat162float(wqb[k * 64 + n]), acc);
            }
            sm[OFF_RED + kc * 64 + n] = acc;
        }
        __syncthreads();   // B1.5: partials ready
        if (tid < 64) {
            float acc = ab1v;
#pragma unroll
            for (int kc = 0; kc < 8; ++kc) acc += sm[OFF_RED + kc * 64 + tid];
            sm[OFF_QB + tid] = acc;
        }
        // --- fold Wc[k][n] = Wh + q[k]*Wp, store tf32 bits (overlaps gather) ---
        for (int idx = tid; idx < 64 * 64; idx += 512) {
            int n = idx & 63, k = idx >> 6;
            __nv_bfloat162 hp = whpb[idx];
            smu[OFF_WCU + k * PH + n] =
                f2tf(fmaf(sm[OFF_QV + k], __bfloat162float(hp.y),
                          __bfloat162float(hp.x)));
        }
        CP_WAIT0();        // gather landed
        __syncthreads();   // B2: all operands staged

        // ====== fused attention MLP: warps 0..12 own rows [16w, 16w+16) ======
        if (w < 13) {
            const int mt = w;

            unsigned int au[32];
            {
                const float* abase = sm + OFF_HIST + (mt * 16 + l4) * PH + lm;
#pragma unroll
                for (int k = 0; k < 8; ++k) {
                    au[4 * k + 0] = f2tf(abase[k * 8]);
                    au[4 * k + 1] = f2tf(abase[8 * PH + k * 8]);
                    au[4 * k + 2] = f2tf(abase[k * 8 + 4]);
                    au[4 * k + 3] = f2tf(abase[8 * PH + k * 8 + 4]);
                }
            }

            float d0[4], d1[4], d2[4], d3[4];
#pragma unroll
            for (int nt2 = 0; nt2 < 4; ++nt2) {
                float bb0 = sm[OFF_AB2 + nt2 * 8 + 2 * lm];
                float bb1 = sm[OFF_AB2 + nt2 * 8 + 2 * lm + 1];
                d0[nt2] = bb0; d1[nt2] = bb1; d2[nt2] = bb0; d3[nt2] = bb1;
            }

            const unsigned int* wc_col = smu + OFF_WCU + lm * PH;
            const unsigned int* w2_col = smu + OFF_W2U + lm * 36 + l4;

            for (int kk = 0; kk < 8; ++kk) {
                float c0 = sm[OFF_QB + kk * 8 + 2 * lm];
                float c1 = sm[OFF_QB + kk * 8 + 2 * lm + 1];
                float c2 = c0, c3 = c1;
                const unsigned int* wcb = wc_col + kk * 8 + l4;
#pragma unroll
                for (int k = 0; k < 8; ++k) {
                    unsigned int b0v = wcb[k * 8 * PH];
                    unsigned int b1v = wcb[k * 8 * PH + 4 * PH];
                    mma_tf32(c0, c1, c2, c3,
                             au[4 * k], au[4 * k + 1], au[4 * k + 2], au[4 * k + 3],
                             b0v, b1v);
                }
                c0 = fmaxf(c0, 0.f); c1 = fmaxf(c1, 0.f);
                c2 = fmaxf(c2, 0.f); c3 = fmaxf(c3, 0.f);

                int src1 = (l & ~3) + (lm >> 1);
                int src2 = src1 + 2;
                float v0a = __shfl_sync(0xffffffffu, c0, src1);
                float v1a = __shfl_sync(0xffffffffu, c1, src1);
                float v2a = __shfl_sync(0xffffffffu, c2, src1);
                float v3a = __shfl_sync(0xffffffffu, c3, src1);
                float v0b = __shfl_sync(0xffffffffu, c0, src2);
                float v1b = __shfl_sync(0xffffffffu, c1, src2);
                float v2b = __shfl_sync(0xffffffffu, c2, src2);
                float v3b = __shfl_sync(0xffffffffu, c3, src2);
                bool hi = (lm & 1);
                unsigned int a0 = f2tf(hi ? v1a : v0a);
                unsigned int a1 = f2tf(hi ? v3a : v2a);
                unsigned int a2 = f2tf(hi ? v1b : v0b);
                unsigned int a3 = f2tf(hi ? v3b : v2b);

                const unsigned int* w2b = w2_col + kk * 8 * 36;
#pragma unroll
                for (int nt2 = 0; nt2 < 4; ++nt2) {
                    unsigned int b0v = w2b[nt2 * 8];
                    unsigned int b1v = w2b[nt2 * 8 + 4 * 36];
                    mma_tf32(d0[nt2], d1[nt2], d2[nt2], d3[nt2],
                             a0, a1, a2, a3, b0v, b1v);
                }
            }

            float p01 = 0.f, p23 = 0.f;
#pragma unroll
            for (int nt2 = 0; nt2 < 4; ++nt2) {
                float w0 = sm[OFF_AOW + nt2 * 8 + 2 * lm];
                float w1 = sm[OFF_AOW + nt2 * 8 + 2 * lm + 1];
                p01 = fmaf(fmaxf(d0[nt2], 0.f), w0, fmaf(fmaxf(d1[nt2], 0.f), w1, p01));
                p23 = fmaf(fmaxf(d2[nt2], 0.f), w0, fmaf(fmaxf(d3[nt2], 0.f), w1, p23));
            }
            p01 += __shfl_xor_sync(0xffffffffu, p01, 1);
            p01 += __shfl_xor_sync(0xffffffffu, p01, 2);
            p23 += __shfl_xor_sync(0xffffffffu, p23, 1);
            p23 += __shfl_xor_sync(0xffffffffu, p23, 2);
            if (lm == 0) {
                int r0 = mt * 16 + l4;
                int r1 = r0 + 8;
                if (r0 < T_)
                    sm[OFF_SC + r0] = (smi[OFF_MSK + r0] != 0) ? p01 + aob0 : -1e9f;
                if (r1 < T_)
                    sm[OFF_SC + r1] = (smi[OFF_MSK + r1] != 0) ? p23 + aob0 : -1e9f;
            }
        }
        __syncthreads();   // B3: scores ready

        // ---- softmax ----
        float v = (tid < T_) ? sm[OFF_SC + tid] : -1e30f;
        float m = v;
        m = fmaxf(m, __shfl_xor_sync(0xffffffffu, m, 16));
        m = fmaxf(m, __shfl_xor_sync(0xffffffffu, m, 8));
        m = fmaxf(m, __shfl_xor_sync(0xffffffffu, m, 4));
        m = fmaxf(m, __shfl_xor_sync(0xffffffffu, m, 2));
        m = fmaxf(m, __shfl_xor_sync(0xffffffffu, m, 1));
        if (l == 0) sm[OFF_WRED + w] = m;
        __syncthreads();   // B4
        float gm = sm[OFF_WRED + 0];
#pragma unroll
        for (int i = 1; i < 16; ++i) gm = fmaxf(gm, sm[OFF_WRED + i]);
        float e = (tid < T_) ? __expf(v - gm) : 0.f;
        if (tid < T_) sm[OFF_SC + tid] = e;
        float s = e;
        s += __shfl_xor_sync(0xffffffffu, s, 16);
        s += __shfl_xor_sync(0xffffffffu, s, 8);
        s += __shfl_xor_sync(0xffffffffu, s, 4);
        s += __shfl_xor_sync(0xffffffffu, s, 2);
        s += __shfl_xor_sync(0xffffffffu, s, 1);
        if (l == 0) sm[OFF_WRED + 16 + w] = s;
        __syncthreads();   // B5

        // ---- interest (normalization folded in) ----
        {
            float ss = sm[OFF_WRED + 16];
#pragma unroll
            for (int i = 1; i < 16; ++i) ss += sm[OFF_WRED + 16 + i];
            float inv = 1.f / ss;
            int j = tid & 63, g = tid >> 6;
            float acc = 0.f;
            for (int t = g * 25; t < (g + 1) * 25; ++t)
                acc = fmaf(sm[OFF_SC + t], sm[OFF_HIST + t * PH + j], acc);
            sm[OFF_RED + g * 64 + j] = acc * inv;
        }
        __syncthreads();   // B6
        if (tid < 64) {
            float iv = 0.f;
#pragma unroll
            for (int g = 0; g < 8; ++g) iv += sm[OFF_RED + g * 64 + tid];
            g_inter[b * 64 + tid] = iv;
        }
    }
}

// ============================================================
// final MLP v5 (unchanged from R10): tf32x2, 16 rows/CTA, grid 256,
// unified 12-chunk cp.async double-buffered weight pipeline.
// ============================================================
#define DR  16
#define FPX 136
#define FPW 264
#define FX    0        // 16*136 = 2176
#define FG1   2176     // 16*264 = 4224 -> 6400
#define FWT0  6400     // 8448 -> 14848
#define FWT1  14848    // 8448 -> 23296
#define FMB1  23296    // 256
#define FMB2  23552    // 128
#define FOW   23680    // 128
#define FRED  23808    // 128
#define FTGT  23936    // 16 (int view)
#define SMEM_F_FLOATS 23952
#define SMEM_F_BYTES  (SMEM_F_FLOATS * 4)

__global__ __launch_bounds__(256, 2) void din_final(
    const int* __restrict__ target,
    const float* __restrict__ table,
    const float* __restrict__ mw1, const float* __restrict__ mb1,
    const float* __restrict__ mw2, const float* __restrict__ mb2,
    const float* __restrict__ ow,  const float* __restrict__ ob,
    float* __restrict__ out) {
    extern __shared__ float sm[];
    int* smi = (int*)sm;
    const int tid = threadIdx.x;
    const int w   = tid >> 5;   // 0..7
    const int l   = tid & 31;
    const int l4  = l >> 2;
    const int lm  = l & 3;
    const int b0  = blockIdx.x * DR;

    if (tid < DR) smi[FTGT + tid] = target[b0 + tid];
    sm[FMB1 + tid] = mb1[tid];
    if (tid < 128) { sm[FMB2 + tid] = mb2[tid]; sm[FOW + tid] = ow[tid]; }
    __syncthreads();

    // ---- X = concat(item, interest), fp32 ----
    {
        const float4* tab4 = (const float4*)table;
        const float4* int4p = (const float4*)g_inter;
        for (int idx = tid; idx < DR * 32; idx += 256) {
            int rr = idx >> 5, v = idx & 31;
            float4 x = (v < 16)
                ? tab4[(size_t)smi[FTGT + rr] * 16 + v]
                : int4p[(size_t)(b0 + rr) * 16 + (v - 16)];
            *(float4*)(sm + FX + rr * FPX + v * 4) = x;
        }
    }

    // ---- issue chunk 0 (mw1 rows 0..32) into FWT0 ----
    {
        const float4* src = (const float4*)mw1;
        float* dst = sm + FWT0;
        for (int idx = tid; idx < 2048; idx += 256) {
            int r = idx >> 6, v = idx & 63;
            cp_async16(smem_u32(dst + r * FPW + v * 4), src + idx);
        }
        CP_COMMIT();
    }

    const int n0w  = w * 32;
    const int n0w2 = w * 16;
    float acc1[16], acc2[8];

    for (int c = 0; c < 12; ++c) {
        CP_WAIT0();
        __syncthreads();   // chunk c visible; prior compute done (buffer reuse safe)

        // issue chunk c+1 into the other buffer (overlaps compute of chunk c)
        if (c < 11) {
            int nc = c + 1;
            float* dst = sm + ((nc & 1) ? FWT1 : FWT0);
            if (nc < 4) {
                const float4* src = (const float4*)(mw1 + nc * 32 * 256);
                for (int idx = tid; idx < 2048; idx += 256) {
                    int r = idx >> 6, v = idx & 63;
                    cp_async16(smem_u32(dst + r * FPW + v * 4), src + idx);
                }
            } else {
                const float4* src = (const float4*)(mw2 + (nc - 4) * 32 * 128);
                for (int idx = tid; idx < 1024; idx += 256) {
                    int r = idx >> 5, v = idx & 31;
                    cp_async16(smem_u32(dst + r * FPX + v * 4), src + idx);
                }
            }
            CP_COMMIT();
        }

        const float* wt = sm + ((c & 1) ? FWT1 : FWT0);

        if (c == 0) {
#pragma unroll
            for (int nt = 0; nt < 4; ++nt) {
                float bb0 = sm[FMB1 + n0w + nt * 8 + 2 * lm];
                float bb1 = sm[FMB1 + n0w + nt * 8 + 2 * lm + 1];
                acc1[nt * 4 + 0] = bb0; acc1[nt * 4 + 1] = bb1;
                acc1[nt * 4 + 2] = bb0; acc1[nt * 4 + 3] = bb1;
            }
        }
        if (c == 4) {
#pragma unroll
            for (int nt = 0; nt < 2; ++nt) {
                float bb0 = sm[FMB2 + n0w2 + nt * 8 + 2 * lm];
                float bb1 = sm[FMB2 + n0w2 + nt * 8 + 2 * lm + 1];
                acc2[nt * 4 + 0] = bb0; acc2[nt * 4 + 1] = bb1;
                acc2[nt * 4 + 2] = bb0; acc2[nt * 4 + 3] = bb1;
            }
        }

        if (c < 4) {
            // ---- stage 1: X chunk [32c..32c+32) @ mw1 chunk ----
#pragma unroll
            for (int s = 0; s < 4; ++s) {
                const float* ab = sm + FX + l4 * FPX + c * 32 + s * 8 + lm;
                unsigned int ah0, al0, ah1, al1, ah2, al2, ah3, al3;
                split_tf32(ab[0],           ah0, al0);
                split_tf32(ab[8 * FPX],     ah1, al1);
                split_tf32(ab[4],           ah2, al2);
                split_tf32(ab[8 * FPX + 4], ah3, al3);
#pragma unroll
                for (int nt = 0; nt < 4; ++nt) {
                    float b0f = wt[(s * 8 + lm) * FPW + n0w + nt * 8 + l4];
                    float b1f = wt[(s * 8 + lm + 4) * FPW + n0w + nt * 8 + l4];
                    unsigned int b0h, b0l, b1h, b1l;
                    split_tf32(b0f, b0h, b0l);
                    split_tf32(b1f, b1h, b1l);
                    int base = nt * 4;
                    mma_tf32(acc1[base + 0], acc1[base + 1], acc1[base + 2], acc1[base + 3],
                             ah0, ah1, ah2, ah3, b0h, b1h);
                    mma_tf32(acc1[base + 0], acc1[base + 1], acc1[base + 2], acc1[base + 3],
                             al0, al1, al2, al3, b0h, b1h);
                    mma_tf32(acc1[base + 0], acc1[base + 1], acc1[base + 2], acc1[base + 3],
                             ah0, ah1, ah2, ah3, b0l, b1l);
                }
            }
            if (c == 3) {
                // G1 = relu(acc1), fp32 (consumed after next chunk's barrier)
#pragma unroll
                for (int nt = 0; nt < 4; ++nt) {
                    int base = nt * 4;
                    int col = n0w + nt * 8 + 2 * lm;
                    *(float2*)(sm + FG1 + l4 * FPW + col) =
                        make_float2(fmaxf(acc1[base + 0], 0.f), fmaxf(acc1[base + 1], 0.f));
                    *(float2*)(sm + FG1 + (l4 + 8) * FPW + col) =
                        make_float2(fmaxf(acc1[base + 2], 0.f), fmaxf(acc1[base + 3], 0.f));
                }
            }
        } else {
            // ---- stage 2: G1 chunk [32(c-4)..) @ mw2 chunk ----
            int ck = c - 4;
#pragma unroll
            for (int s = 0; s < 4; ++s) {
                const float* ab = sm + FG1 + l4 * FPW + ck * 32 + s * 8 + lm;
                unsigned int ah0, al0, ah1, al1, ah2, al2, ah3, al3;
                split_tf32(ab[0],           ah0, al0);
                split_tf32(ab[8 * FPW],     ah1, al1);
                split_tf32(ab[4],           ah2, al2);
                split_tf32(ab[8 * FPW + 4], ah3, al3);
#pragma unroll
                for (int nt = 0; nt < 2; ++nt) {
                    float b0f = wt[(s * 8 + lm) * FPX + n0w2 + nt * 8 + l4];
                    float b1f = wt[(s * 8 + lm + 4) * FPX + n0w2 + nt * 8 + l4];
                    unsigned int b0h, b0l, b1h, b1l;
                    split_tf32(b0f, b0h, b0l);
                    split_tf32(b1f, b1h, b1l);
                    int base = nt * 4;
                    mma_tf32(acc2[base + 0], acc2[base + 1], acc2[base + 2], acc2[base + 3],
                             ah0, ah1, ah2, ah3, b0h, b1h);
                    mma_tf32(acc2[base + 0], acc2[base + 1], acc2[base + 2], acc2[base + 3],
                             al0, al1, al2, al3, b0h, b1h);
                    mma_tf32(acc2[base + 0], acc2[base + 1], acc2[base + 2], acc2[base + 3],
                             ah0, ah1, ah2, ah3, b0l, b1l);
                }
            }
        }
    }

    // ---- stage 3: out = relu(acc2) @ ow + ob ----
    float pA = 0.f, pB = 0.f;
#pragma unroll
    for (int nt = 0; nt < 2; ++nt) {
        int base = nt * 4;
        float w0 = sm[FOW + n0w2 + nt * 8 + 2 * lm];
        float w1 = sm[FOW + n0w2 + nt * 8 + 2 * lm + 1];
        pA = fmaf(fmaxf(acc2[base + 0], 0.f), w0,
             fmaf(fmaxf(acc2[base + 1], 0.f), w1, pA));
        pB = fmaf(fmaxf(acc2[base + 2], 0.f), w0,
             fmaf(fmaxf(acc2[base + 3], 0.f), w1, pB));
    }
    pA += __shfl_xor_sync(0xffffffffu, pA, 1);
    pA += __shfl_xor_sync(0xffffffffu, pA, 2);
    pB += __shfl_xor_sync(0xffffffffu, pB, 1);
    pB += __shfl_xor_sync(0xffffffffu, pB, 2);
    if (lm == 0) {
        sm[FRED + w * 16 + l4]     = pA;
        sm[FRED + w * 16 + l4 + 8] = pB;
    }
    __syncthreads();
    if (tid < DR) {
        float p = ob[0];
#pragma unroll
        for (int w8 = 0; w8 < 8; ++w8) p += sm[FRED + w8 * 16 + tid];
        out[b0 + tid] = p;
    }
}

// ============================================================
// launch
// ============================================================
extern "C" void kernel_launch(void* const* d_in, const int* in_sizes, int n_in,
                              void* d_out, int out_size) {
    const int*   target  = (const int*)d_in[0];
    const int*   hist_id = (const int*)d_in[1];
    const int*   mask    = (const int*)d_in[2];     // bool promoted; test != 0
    const float* table   = (const float*)d_in[3];
    const float* aw1     = (const float*)d_in[4];
    const float* ab1     = (const float*)d_in[5];
    const float* aw2     = (const float*)d_in[6];
    const float* ab2     = (const float*)d_in[7];
    const float* aow     = (const float*)d_in[8];
    const float* aob     = (const float*)d_in[9];
    const float* mw1     = (const float*)d_in[10];
    const float* mb1     = (const float*)d_in[11];
    const float* mw2     = (const float*)d_in[12];
    const float* mb2     = (const float*)d_in[13];
    const float* ow      = (const float*)d_in[14];
    const float* ob      = (const float*)d_in[15];
    float* out = (float*)d_out;

    cudaFuncSetAttribute(din_main, cudaFuncAttributeMaxDynamicSharedMemorySize, SMEM_B_BYTES);
    cudaFuncSetAttribute(din_final, cudaFuncAttributeMaxDynamicSharedMemorySize, SMEM_F_BYTES);

    din_main<<<GRID_MAIN, 512, SMEM_B_BYTES>>>(hist_id, mask, table, target, aw1,
                                               ab1, aw2, ab2, aow, aob);
    din_final<<<B_ / DR, 256, SMEM_F_BYTES>>>(target, table, mw1, mb1,
                                              mw2, mb2, ow, ob, out);
}

// round 12
// speedup vs baseline: 1.2677x; 1.2252x over previous
#include <cuda_runtime.h>
#include <cuda_bf16.h>
#include <math.h>
#include <stdint.h>

// Problem constants
#define B_  4096
#define T_  200
#define E_  64
#define A1_ 64
#define A2_ 32
#define M1_ 256
#define M2_ 128
#define GRID_MAIN 296   // 2 CTAs per SM x 148 SMs

// -------- device scratch (no allocations allowed) --------
__device__ float g_inter[B_ * 64]; // interest vectors

// ---- tf32 helpers (din_final) ----
__device__ __forceinline__ unsigned int f2tf(float f) {
    unsigned int r;
    asm("cvt.rna.tf32.f32 %0, %1;" : "=r"(r) : "f"(f));
    return r;
}
__device__ __forceinline__ void split_tf32(float x, unsigned int& hi, unsigned int& lo) {
    hi = f2tf(x);
    lo = f2tf(x - __uint_as_float(hi));
}
__device__ __forceinline__ void mma_tf32(
    float& c0, float& c1, float& c2, float& c3,
    unsigned int a0, unsigned int a1, unsigned int a2, unsigned int a3,
    unsigned int b0, unsigned int b1) {
    asm("mma.sync.aligned.m16n8k8.row.col.f32.tf32.tf32.f32 "
        "{%0,%1,%2,%3},{%4,%5,%6,%7},{%8,%9},{%0,%1,%2,%3};"
        : "+f"(c0), "+f"(c1), "+f"(c2), "+f"(c3)
        : "r"(a0), "r"(a1), "r"(a2), "r"(a3), "r"(b0), "r"(b1));
}
// ---- bf16 helpers (din_main) ----
__device__ __forceinline__ unsigned int pack_bf16(float lo, float hi) {
    unsigned int r;   // d = {hi, lo}
    asm("cvt.rn.bf16x2.f32 %0, %1, %2;" : "=r"(r) : "f"(hi), "f"(lo));
    return r;
}
__device__ __forceinline__ void mma_bf16(
    float& c0, float& c1, float& c2, float& c3,
    unsigned int a0, unsigned int a1, unsigned int a2, unsigned int a3,
    unsigned int b0, unsigned int b1) {
    asm("mma.sync.aligned.m16n8k16.row.col.f32.bf16.bf16.f32 "
        "{%0,%1,%2,%3},{%4,%5,%6,%7},{%8,%9},{%0,%1,%2,%3};"
        : "+f"(c0), "+f"(c1), "+f"(c2), "+f"(c3)
        : "r"(a0), "r"(a1), "r"(a2), "r"(a3), "r"(b0), "r"(b1));
}
// ---- cp.async helpers ----
__device__ __forceinline__ void cp_async16(unsigned int dst, const void* src) {
    asm volatile("cp.async.ca.shared.global [%0], [%1], 16;" :: "r"(dst), "l"(src) : "memory");
}
__device__ __forceinline__ unsigned int smem_u32(const void* p) {
    return (unsigned int)__cvta_generic_to_shared(p);
}
#define CP_COMMIT() asm volatile("cp.async.commit_group;" ::: "memory")
#define CP_WAIT0()  asm volatile("cp.async.wait_group 0;" ::: "memory")

// ============================================================
// main kernel: PERSISTENT, 296 CTAs x 512 threads, 2 CTAs/SM.
// Attention MLP on bf16 m16n8k16 mma; layer1 C-frag IS layer2 A-frag
// (no shuffles). HIST stays fp32 for the interest phase.
// ============================================================
#define PH  68   // HIST pitch (fp32 words)
#define PWB 36   // WCB/W2B pitch (32-bit words; 4l4+lm conflict-free)
// smem layout (float/word offsets)
#define OFF_HIST  0        // 208*68 = 14144
#define OFF_WCB   14144    // 64*36 = 2304 -> 16448 (Wc bf16 [n][k] pairs)
#define OFF_W2B   16448    // 32*36 = 1152 -> 17600 (aw2 bf16 [n][k] pairs)
#define OFF_QV    17600    // 64
#define OFF_QB    17664    // 64
#define OFF_AB2   17728    // 32
#define OFF_AOW   17760    // 32
#define OFF_SC    17792    // 208
#define OFF_MSK   18000    // 208 (int view)
#define OFF_WRED  18208    // 32
#define OFF_RED   18240    // 512
#define OFF_WHPB  18752    // 4096 (bf16x2 (Wh,Wp), layout [n*64+k])
#define OFF_WQB   22848    // 2048 (bf16 Wq [k][n])
#define SMEM_B_FLOATS 24896
#define SMEM_B_BYTES  (SMEM_B_FLOATS * 4)

__global__ __launch_bounds__(512, 2) void din_main(
    const int* __restrict__ hist_id,
    const int* __restrict__ mask,        // bool promoted to 4-byte; test != 0
    const float* __restrict__ table,
    const int* __restrict__ target,
    const float* __restrict__ aw1,
    const float* __restrict__ ab1,
    const float* __restrict__ aw2,
    const float* __restrict__ ab2,
    const float* __restrict__ aow,
    const float* __restrict__ aob) {
    extern __shared__ float sm[];
    unsigned int* smu = (unsigned int*)sm;
    int* smi = (int*)sm;
    unsigned int* whpb = smu + OFF_WHPB;              // bf16x2 (Wh,Wp) at [n*64+k]
    __nv_bfloat16* wqb = (__nv_bfloat16*)(smu + OFF_WQB);  // Wq [k][n]
    const int tid = threadIdx.x;
    const int w   = tid >> 5;
    const int l   = tid & 31;
    const int l4  = l >> 2;   // 0..7
    const int lm  = l & 3;    // 0..3

    // ---- loop-invariant staging (once per CTA) ----
    if (tid < 32)        sm[OFF_AB2 + tid]      = ab2[tid];
    else if (tid < 64)   sm[OFF_AOW + tid - 32] = aow[tid - 32];
    // W2B: aw2 bf16 [n][k] pairs, pitch 36 words
    for (int idx = tid; idx < 32 * 32; idx += 512) {
        int kp = idx & 31, n = idx >> 5;
        float v0 = aw2[(2 * kp) * 32 + n];
        float v1 = aw2[(2 * kp + 1) * 32 + n];
        smu[OFF_W2B + n * PWB + kp] = pack_bf16(v0, v1);
    }
    // WHPB ([n*64+k]) + WQB ([k][n]) from aw1
    for (int idx = tid; idx < 64 * 64; idx += 512) {
        int k = idx & 63, n = idx >> 6;
        float a = aw1[k * 64 + n];
        float bb = aw1[(64 + k) * 64 + n];
        float c = aw1[(128 + k) * 64 + n];
        float d = aw1[(192 + k) * 64 + n];
        whpb[n * 64 + k] = pack_bf16(a + c, d);   // lo=Wh, hi=Wp
        wqb[k * 64 + n] = __float2bfloat16(bb - c);
    }
    // zero-pad HIST rows 200..207 ONCE
    {
        float4* hist4 = (float4*)(sm + OFF_HIST);
        for (int idx = tid; idx < 8 * 17; idx += 512) {
            int t = 200 + idx / 17, v = idx % 17;
            hist4[t * 17 + v] = make_float4(0.f, 0.f, 0.f, 0.f);
        }
    }
    const float aob0 = aob[0];
    const float ab1v = (tid < 64) ? ab1[tid] : 0.f;

    for (int b = blockIdx.x; b < B_; b += GRID_MAIN) {
        __syncthreads();   // B0: prior iteration fully done

        // --- per-batch staging: item embedding + mask ---
        if (tid < 64)
            sm[OFF_QV + tid] = table[(size_t)target[b] * 64 + tid];
        else if (tid < 264)
            smi[OFF_MSK + tid - 64] = mask[b * T_ + tid - 64];
        __syncthreads();   // B1: QV ready; prior-iter HIST reads done

        // --- issue hist gather via cp.async (register-free), overlap below ---
        {
            const float4* tab4 = (const float4*)table;
            float* histb = sm + OFF_HIST;
            for (int idx = tid; idx < T_ * 16; idx += 512) {
                int t = idx >> 4, v = idx & 15;
                cp_async16(smem_u32(histb + t * PH + v * 4),
                           tab4 + (size_t)hist_id[b * T_ + t] * 16 + v);
            }
            CP_COMMIT();
        }
        // --- qb partials: all 512 threads, LDS-only Wq (overlaps gather) ---
        {
            int n = tid & 63, kc = tid >> 6;
            float acc = 0.f;
#pragma unroll
            for (int i = 0; i < 8; ++i) {
                int k = kc * 8 + i;
                acc = fmaf(sm[OFF_QV + k], __bfloat162float(wqb[k * 64 + n]), acc);
            }
            sm[OFF_RED + kc * 64 + n] = acc;
        }
        __syncthreads();   // B1.5: partials ready
        if (tid < 64) {
            float acc = ab1v;
#pragma unroll
            for (int kc = 0; kc < 8; ++kc) acc += sm[OFF_RED + kc * 64 + tid];
            sm[OFF_QB + tid] = acc;
        }
        // --- fold Wc[n][k] = Wh + q[k]*Wp -> bf16 pairs (overlaps gather) ---
        for (int idx = tid; idx < 64 * 32; idx += 512) {
            int kp = idx & 31, n = idx >> 5;
            uint2 hp2 = *(const uint2*)(whpb + n * 64 + 2 * kp);
            __nv_bfloat162 h0 = *(__nv_bfloat162*)&hp2.x;   // (Wh,Wp)@k0
            __nv_bfloat162 h1 = *(__nv_bfloat162*)&hp2.y;   // (Wh,Wp)@k1
            float f0 = fmaf(sm[OFF_QV + 2 * kp],     __bfloat162float(h0.y),
                            __bfloat162float(h0.x));
            float f1 = fmaf(sm[OFF_QV + 2 * kp + 1], __bfloat162float(h1.y),
                            __bfloat162float(h1.x));
            smu[OFF_WCB + n * PWB + kp] = pack_bf16(f0, f1);
        }
        CP_WAIT0();        // gather landed
        __syncthreads();   // B2: all operands staged

        // ====== fused attention MLP (bf16 k16): warps 0..12, rows [16w,+16) ===
        if (w < 13) {
            const int mt = w;

            // A frags: 4 k16-steps x 4 regs (bf16x2 from fp32 HIST)
            unsigned int a[4][4];
            {
                const float* abase = sm + OFF_HIST + (mt * 16 + l4) * PH + 2 * lm;
#pragma unroll
                for (int ks = 0; ks < 4; ++ks) {
                    float2 v00 = *(const float2*)(abase + 16 * ks);
                    float2 v10 = *(const float2*)(abase + 16 * ks + 8 * PH);
                    float2 v01 = *(const float2*)(abase + 16 * ks + 8);
                    float2 v11 = *(const float2*)(abase + 16 * ks + 8 * PH + 8);
                    a[ks][0] = pack_bf16(v00.x, v00.y);
                    a[ks][1] = pack_bf16(v10.x, v10.y);
                    a[ks][2] = pack_bf16(v01.x, v01.y);
                    a[ks][3] = pack_bf16(v11.x, v11.y);
                }
            }

            float d0[4], d1[4], d2[4], d3[4];
#pragma unroll
            for (int nt = 0; nt < 4; ++nt) {
                float bb0 = sm[OFF_AB2 + nt * 8 + 2 * lm];
                float bb1 = sm[OFF_AB2 + nt * 8 + 2 * lm + 1];
                d0[nt] = bb0; d1[nt] = bb1; d2[nt] = bb0; d3[nt] = bb1;
            }

            const unsigned int* wcbw = smu + OFF_WCB + l4 * PWB + lm;
            const unsigned int* w2bw = smu + OFF_W2B + l4 * PWB + lm;

#pragma unroll
            for (int j = 0; j < 4; ++j) {
                unsigned int A2[4];
#pragma unroll
                for (int t2 = 0; t2 < 2; ++t2) {
                    const int kk = 2 * j + t2;
                    float c0 = sm[OFF_QB + kk * 8 + 2 * lm];
                    float c1 = sm[OFF_QB + kk * 8 + 2 * lm + 1];
                    float c2 = c0, c3 = c1;
                    const unsigned int* wb = wcbw + kk * 8 * PWB;
#pragma unroll
                    for (int ks = 0; ks < 4; ++ks) {
                        unsigned int b0 = wb[8 * ks];
                        unsigned int b1 = wb[8 * ks + 4];
                        mma_bf16(c0, c1, c2, c3,
                                 a[ks][0], a[ks][1], a[ks][2], a[ks][3], b0, b1);
                    }
                    // relu + pack: C-frag == layer2 A-frag (no shuffles)
                    A2[2 * t2 + 0] = pack_bf16(fmaxf(c0, 0.f), fmaxf(c1, 0.f));
                    A2[2 * t2 + 1] = pack_bf16(fmaxf(c2, 0.f), fmaxf(c3, 0.f));
                }
                const unsigned int* w2 = w2bw + 8 * j;
#pragma unroll
                for (int nt = 0; nt < 4; ++nt) {
                    unsigned int b0 = w2[nt * 8 * PWB];
                    unsigned int b1 = w2[nt * 8 * PWB + 4];
                    mma_bf16(d0[nt], d1[nt], d2[nt], d3[nt],
                             A2[0], A2[1], A2[2], A2[3], b0, b1);
                }
            }

            float p01 = 0.f, p23 = 0.f;
#pragma unroll
            for (int nt = 0; nt < 4; ++nt) {
                float w0 = sm[OFF_AOW + nt * 8 + 2 * lm];
                float w1 = sm[OFF_AOW + nt * 8 + 2 * lm + 1];
                p01 = fmaf(fmaxf(d0[nt], 0.f), w0, fmaf(fmaxf(d1[nt], 0.f), w1, p01));
                p23 = fmaf(fmaxf(d2[nt], 0.f), w0, fmaf(fmaxf(d3[nt], 0.f), w1, p23));
            }
            p01 += __shfl_xor_sync(0xffffffffu, p01, 1);
            p01 += __shfl_xor_sync(0xffffffffu, p01, 2);
            p23 += __shfl_xor_sync(0xffffffffu, p23, 1);
            p23 += __shfl_xor_sync(0xffffffffu, p23, 2);
            if (lm == 0) {
                int r0 = mt * 16 + l4;
                int r1 = r0 + 8;
                if (r0 < T_)
                    sm[OFF_SC + r0] = (smi[OFF_MSK + r0] != 0) ? p01 + aob0 : -1e9f;
                if (r1 < T_)
                    sm[OFF_SC + r1] = (smi[OFF_MSK + r1] != 0) ? p23 + aob0 : -1e9f;
            }
        }
        __syncthreads();   // B3: scores ready

        // ---- softmax ----
        float v = (tid < T_) ? sm[OFF_SC + tid] : -1e30f;
        float m = v;
        m = fmaxf(m, __shfl_xor_sync(0xffffffffu, m, 16));
        m = fmaxf(m, __shfl_xor_sync(0xffffffffu, m, 8));
        m = fmaxf(m, __shfl_xor_sync(0xffffffffu, m, 4));
        m = fmaxf(m, __shfl_xor_sync(0xffffffffu, m, 2));
        m = fmaxf(m, __shfl_xor_sync(0xffffffffu, m, 1));
        if (l == 0) sm[OFF_WRED + w] = m;
        __syncthreads();   // B4
        float gm = sm[OFF_WRED + 0];
#pragma unroll
        for (int i = 1; i < 16; ++i) gm = fmaxf(gm, sm[OFF_WRED + i]);
        float e = (tid < T_) ? __expf(v - gm) : 0.f;
        if (tid < T_) sm[OFF_SC + tid] = e;
        float s = e;
        s += __shfl_xor_sync(0xffffffffu, s, 16);
        s += __shfl_xor_sync(0xffffffffu, s, 8);
        s += __shfl_xor_sync(0xffffffffu, s, 4);
        s += __shfl_xor_sync(0xffffffffu, s, 2);
        s += __shfl_xor_sync(0xffffffffu, s, 1);
        if (l == 0) sm[OFF_WRED + 16 + w] = s;
        __syncthreads();   // B5

        // ---- interest (normalization folded in; fp32 HIST) ----
        {
            float ss = sm[OFF_WRED + 16];
#pragma unroll
            for (int i = 1; i < 16; ++i) ss += sm[OFF_WRED + 16 + i];
            float inv = 1.f / ss;
            int j = tid & 63, g = tid >> 6;
            float acc = 0.f;
            for (int t = g * 25; t < (g + 1) * 25; ++t)
                acc = fmaf(sm[OFF_SC + t], sm[OFF_HIST + t * PH + j], acc);
            sm[OFF_RED + g * 64 + j] = acc * inv;
        }
        __syncthreads();   // B6
        if (tid < 64) {
            float iv = 0.f;
#pragma unroll
            for (int g = 0; g < 8; ++g) iv += sm[OFF_RED + g * 64 + tid];
            g_inter[b * 64 + tid] = iv;
        }
    }
}

// ============================================================
// final MLP v5 (unchanged): tf32x2, 16 rows/CTA, grid 256,
// unified 12-chunk cp.async double-buffered weight pipeline.
// ============================================================
#define DR  16
#define FPX 136
#define FPW 264
#define FX    0        // 16*136 = 2176
#define FG1   2176     // 16*264 = 4224 -> 6400
#define FWT0  6400     // 8448 -> 14848
#define FWT1  14848    // 8448 -> 23296
#define FMB1  23296    // 256
#define FMB2  23552    // 128
#define FOW   23680    // 128
#define FRED  23808    // 128
#define FTGT  23936    // 16 (int view)
#define SMEM_F_FLOATS 23952
#define SMEM_F_BYTES  (SMEM_F_FLOATS * 4)

__global__ __launch_bounds__(256, 2) void din_final(
    const int* __restrict__ target,
    const float* __restrict__ table,
    const float* __restrict__ mw1, const float* __restrict__ mb1,
    const float* __restrict__ mw2, const float* __restrict__ mb2,
    const float* __restrict__ ow,  const float* __restrict__ ob,
    float* __restrict__ out) {
    extern __shared__ float sm[];
    int* smi = (int*)sm;
    const int tid = threadIdx.x;
    const int w   = tid >> 5;   // 0..7
    const int l   = tid & 31;
    const int l4  = l >> 2;
    const int lm  = l & 3;
    const int b0  = blockIdx.x * DR;

    if (tid < DR) smi[FTGT + tid] = target[b0 + tid];
    sm[FMB1 + tid] = mb1[tid];
    if (tid < 128) { sm[FMB2 + tid] = mb2[tid]; sm[FOW + tid] = ow[tid]; }
    __syncthreads();

    // ---- X = concat(item, interest), fp32 ----
    {
        const float4* tab4 = (const float4*)table;
        const float4* int4p = (const float4*)g_inter;
        for (int idx = tid; idx < DR * 32; idx += 256) {
            int rr = idx >> 5, v = idx & 31;
            float4 x = (v < 16)
                ? tab4[(size_t)smi[FTGT + rr] * 16 + v]
                : int4p[(size_t)(b0 + rr) * 16 + (v - 16)];
            *(float4*)(sm + FX + rr * FPX + v * 4) = x;
        }
    }

    // ---- issue chunk 0 (mw1 rows 0..32) into FWT0 ----
    {
        const float4* src = (const float4*)mw1;
        float* dst = sm + FWT0;
        for (int idx = tid; idx < 2048; idx += 256) {
            int r = idx >> 6, v = idx & 63;
            cp_async16(smem_u32(dst + r * FPW + v * 4), src + idx);
        }
        CP_COMMIT();
    }

    const int n0w  = w * 32;
    const int n0w2 = w * 16;
    float acc1[16], acc2[8];

    for (int c = 0; c < 12; ++c) {
        CP_WAIT0();
        __syncthreads();   // chunk c visible; prior compute done (buffer reuse safe)

        // issue chunk c+1 into the other buffer (overlaps compute of chunk c)
        if (c < 11) {
            int nc = c + 1;
            float* dst = sm + ((nc & 1) ? FWT1 : FWT0);
            if (nc < 4) {
                const float4* src = (const float4*)(mw1 + nc * 32 * 256);
                for (int idx = tid; idx < 2048; idx += 256) {
                    int r = idx >> 6, v = idx & 63;
                    cp_async16(smem_u32(dst + r * FPW + v * 4), src + idx);
                }
            } else {
                const float4* src = (const float4*)(mw2 + (nc - 4) * 32 * 128);
                for (int idx = tid; idx < 1024; idx += 256) {
                    int r = idx >> 5, v = idx & 31;
                    cp_async16(smem_u32(dst + r * FPX + v * 4), src + idx);
                }
            }
            CP_COMMIT();
        }

        const float* wt = sm + ((c & 1) ? FWT1 : FWT0);

        if (c == 0) {
#pragma unroll
            for (int nt = 0; nt < 4; ++nt) {
                float bb0 = sm[FMB1 + n0w + nt * 8 + 2 * lm];
                float bb1 = sm[FMB1 + n0w + nt * 8 + 2 * lm + 1];
                acc1[nt * 4 + 0] = bb0; acc1[nt * 4 + 1] = bb1;
                acc1[nt * 4 + 2] = bb0; acc1[nt * 4 + 3] = bb1;
            }
        }
        if (c == 4) {
#pragma unroll
            for (int nt = 0; nt < 2; ++nt) {
                float bb0 = sm[FMB2 + n0w2 + nt * 8 + 2 * lm];
                float bb1 = sm[FMB2 + n0w2 + nt * 8 + 2 * lm + 1];
                acc2[nt * 4 + 0] = bb0; acc2[nt * 4 + 1] = bb1;
                acc2[nt * 4 + 2] = bb0; acc2[nt * 4 + 3] = bb1;
            }
        }

        if (c < 4) {
            // ---- stage 1: X chunk [32c..32c+32) @ mw1 chunk ----
#pragma unroll
            for (int s = 0; s < 4; ++s) {
                const float* ab = sm + FX + l4 * FPX + c * 32 + s * 8 + lm;
                unsigned int ah0, al0, ah1, al1, ah2, al2, ah3, al3;
                split_tf32(ab[0],           ah0, al0);
                split_tf32(ab[8 * FPX],     ah1, al1);
                split_tf32(ab[4],           ah2, al2);
                split_tf32(ab[8 * FPX + 4], ah3, al3);
#pragma unroll
                for (int nt = 0; nt < 4; ++nt) {
                    float b0f = wt[(s * 8 + lm) * FPW + n0w + nt * 8 + l4];
                    float b1f = wt[(s * 8 + lm + 4) * FPW + n0w + nt * 8 + l4];
                    unsigned int b0h, b0l, b1h, b1l;
                    split_tf32(b0f, b0h, b0l);
                    split_tf32(b1f, b1h, b1l);
                    int base = nt * 4;
                    mma_tf32(acc1[base + 0], acc1[base + 1], acc1[base + 2], acc1[base + 3],
                             ah0, ah1, ah2, ah3, b0h, b1h);
                    mma_tf32(acc1[base + 0], acc1[base + 1], acc1[base + 2], acc1[base + 3],
                             al0, al1, al2, al3, b0h, b1h);
                    mma_tf32(acc1[base + 0], acc1[base + 1], acc1[base + 2], acc1[base + 3],
                             ah0, ah1, ah2, ah3, b0l, b1l);
                }
            }
            if (c == 3) {
                // G1 = relu(acc1), fp32 (consumed after next chunk's barrier)
#pragma unroll
                for (int nt = 0; nt < 4; ++nt) {
                    int base = nt * 4;
                    int col = n0w + nt * 8 + 2 * lm;
                    *(float2*)(sm + FG1 + l4 * FPW + col) =
                        make_float2(fmaxf(acc1[base + 0], 0.f), fmaxf(acc1[base + 1], 0.f));
                    *(float2*)(sm + FG1 + (l4 + 8) * FPW + col) =
                        make_float2(fmaxf(acc1[base + 2], 0.f), fmaxf(acc1[base + 3], 0.f));
                }
            }
        } else {
            // ---- stage 2: G1 chunk [32(c-4)..) @ mw2 chunk ----
            int ck = c - 4;
#pragma unroll
            for (int s = 0; s < 4; ++s) {
                const float* ab = sm + FG1 + l4 * FPW + ck * 32 + s * 8 + lm;
                unsigned int ah0, al0, ah1, al1, ah2, al2, ah3, al3;
                split_tf32(ab[0],           ah0, al0);
                split_tf32(ab[8 * FPW],     ah1, al1);
                split_tf32(ab[4],           ah2, al2);
                split_tf32(ab[8 * FPW + 4], ah3, al3);
#pragma unroll
                for (int nt = 0; nt < 2; ++nt) {
                    float b0f = wt[(s * 8 + lm) * FPX + n0w2 + nt * 8 + l4];
                    float b1f = wt[(s * 8 + lm + 4) * FPX + n0w2 + nt * 8 + l4];
                    unsigned int b0h, b0l, b1h, b1l;
                    split_tf32(b0f, b0h, b0l);
                    split_tf32(b1f, b1h, b1l);
                    int base = nt * 4;
                    mma_tf32(acc2[base + 0], acc2[base + 1], acc2[base + 2], acc2[base + 3],
                             ah0, ah1, ah2, ah3, b0h, b1h);
                    mma_tf32(acc2[base + 0], acc2[base + 1], acc2[base + 2], acc2[base + 3],
                             al0, al1, al2, al3, b0h, b1h);
                    mma_tf32(acc2[base + 0], acc2[base + 1], acc2[base + 2], acc2[base + 3],
                             ah0, ah1, ah2, ah3, b0l, b1l);
                }
            }
        }
    }

    // ---- stage 3: out = relu(acc2) @ ow + ob ----
    float pA = 0.f, pB = 0.f;
#pragma unroll
    for (int nt = 0; nt < 2; ++nt) {
        int base = nt * 4;
        float w0 = sm[FOW + n0w2 + nt * 8 + 2 * lm];
        float w1 = sm[FOW + n0w2 + nt * 8 + 2 * lm + 1];
        pA = fmaf(fmaxf(acc2[base + 0], 0.f), w0,
             fmaf(fmaxf(acc2[base + 1], 0.f), w1, pA));
        pB = fmaf(fmaxf(acc2[base + 2], 0.f), w0,
             fmaf(fmaxf(acc2[base + 3], 0.f), w1, pB));
    }
    pA += __shfl_xor_sync(0xffffffffu, pA, 1);
    pA += __shfl_xor_sync(0xffffffffu, pA, 2);
    pB += __shfl_xor_sync(0xffffffffu, pB, 1);
    pB += __shfl_xor_sync(0xffffffffu, pB, 2);
    if (lm == 0) {
        sm[FRED + w * 16 + l4]     = pA;
        sm[FRED + w * 16 + l4 + 8] = pB;
    }
    __syncthreads();
    if (tid < DR) {
        float p = ob[0];
#pragma unroll
        for (int w8 = 0; w8 < 8; ++w8) p += sm[FRED + w8 * 16 + tid];
        out[b0 + tid] = p;
    }
}

// ============================================================
// launch
// ============================================================
extern "C" void kernel_launch(void* const* d_in, const int* in_sizes, int n_in,
                              void* d_out, int out_size) {
    const int*   target  = (const int*)d_in[0];
    const int*   hist_id = (const int*)d_in[1];
    const int*   mask    = (const int*)d_in[2];     // bool promoted; test != 0
    const float* table   = (const float*)d_in[3];
    const float* aw1     = (const float*)d_in[4];
    const float* ab1     = (const float*)d_in[5];
    const float* aw2     = (const float*)d_in[6];
    const float* ab2     = (const float*)d_in[7];
    const float* aow     = (const float*)d_in[8];
    const float* aob     = (const float*)d_in[9];
    const float* mw1     = (const float*)d_in[10];
    const float* mb1     = (const float*)d_in[11];
    const float* mw2     = (const float*)d_in[12];
    const float* mb2     = (const float*)d_in[13];
    const float* ow      = (const float*)d_in[14];
    const float* ob      = (const float*)d_in[15];
    float* out = (float*)d_out;

    cudaFuncSetAttribute(din_main, cudaFuncAttributeMaxDynamicSharedMemorySize, SMEM_B_BYTES);
    cudaFuncSetAttribute(din_final, cudaFuncAttributeMaxDynamicSharedMemorySize, SMEM_F_BYTES);

    din_main<<<GRID_MAIN, 512, SMEM_B_BYTES>>>(hist_id, mask, table, target, aw1,
                                               ab1, aw2, ab2, aow, aob);
    din_final<<<B_ / DR, 256, SMEM_F_BYTES>>>(target, table, mw1, mb1,
                                              mw2, mb2, ow, ob, out);
}

// round 13
// speedup vs baseline: 1.3174x; 1.0392x over previous
#include <cuda_runtime.h>
#include <cuda_bf16.h>
#include <math.h>
#include <stdint.h>

// Problem constants
#define B_  4096
#define T_  200
#define E_  64
#define A1_ 64
#define A2_ 32
#define M1_ 256
#define M2_ 128
#define GRID_MAIN 296   // 2 CTAs per SM x 148 SMs

// -------- device scratch (no allocations allowed) --------
__device__ float g_inter[B_ * 64]; // interest vectors

// ---- tf32 helpers (din_final) ----
__device__ __forceinline__ unsigned int f2tf(float f) {
    unsigned int r;
    asm("cvt.rna.tf32.f32 %0, %1;" : "=r"(r) : "f"(f));
    return r;
}
__device__ __forceinline__ void split_tf32(float x, unsigned int& hi, unsigned int& lo) {
    hi = f2tf(x);
    lo = f2tf(x - __uint_as_float(hi));
}
__device__ __forceinline__ void mma_tf32(
    float& c0, float& c1, float& c2, float& c3,
    unsigned int a0, unsigned int a1, unsigned int a2, unsigned int a3,
    unsigned int b0, unsigned int b1) {
    asm("mma.sync.aligned.m16n8k8.row.col.f32.tf32.tf32.f32 "
        "{%0,%1,%2,%3},{%4,%5,%6,%7},{%8,%9},{%0,%1,%2,%3};"
        : "+f"(c0), "+f"(c1), "+f"(c2), "+f"(c3)
        : "r"(a0), "r"(a1), "r"(a2), "r"(a3), "r"(b0), "r"(b1));
}
// ---- bf16 helpers (din_main) ----
__device__ __forceinline__ unsigned int pack_bf16(float lo, float hi) {
    unsigned int r;   // d = {hi, lo}
    asm("cvt.rn.bf16x2.f32 %0, %1, %2;" : "=r"(r) : "f"(hi), "f"(lo));
    return r;
}
__device__ __forceinline__ void mma_bf16(
    float& c0, float& c1, float& c2, float& c3,
    unsigned int a0, unsigned int a1, unsigned int a2, unsigned int a3,
    unsigned int b0, unsigned int b1) {
    asm("mma.sync.aligned.m16n8k16.row.col.f32.bf16.bf16.f32 "
        "{%0,%1,%2,%3},{%4,%5,%6,%7},{%8,%9},{%0,%1,%2,%3};"
        : "+f"(c0), "+f"(c1), "+f"(c2), "+f"(c3)
        : "r"(a0), "r"(a1), "r"(a2), "r"(a3), "r"(b0), "r"(b1));
}
// ---- cp.async helpers ----
__device__ __forceinline__ void cp_async16(unsigned int dst, const void* src) {
    asm volatile("cp.async.ca.shared.global [%0], [%1], 16;" :: "r"(dst), "l"(src) : "memory");
}
__device__ __forceinline__ unsigned int smem_u32(const void* p) {
    return (unsigned int)__cvta_generic_to_shared(p);
}
#define CP_COMMIT() asm volatile("cp.async.commit_group;" ::: "memory")
#define CP_WAIT0()  asm volatile("cp.async.wait_group 0;" ::: "memory")
#define CP_WAIT1()  asm volatile("cp.async.wait_group 1;" ::: "memory")

// ============================================================
// main kernel: PERSISTENT, 296 CTAs x 512 threads, 2 CTAs/SM.
// bf16 k16 attention MLP; exp+sum fused into mma epilogue
// (no-max softmax); QV/MSK staged via cp.async; float2 interest.
// ============================================================
#define PH  68   // HIST pitch (fp32 words)
#define PWB 36   // WCB/W2B pitch (32-bit words)
// smem layout (float/word offsets)
#define OFF_HIST  0        // 208*68 = 14144
#define OFF_WCB   14144    // 2304 -> 16448
#define OFF_W2B   16448    // 1152 -> 17600
#define OFF_QV    17600    // 64
#define OFF_QB    17664    // 64
#define OFF_AB2   17728    // 32
#define OFF_AOW   17760    // 32
#define OFF_SC    17792    // 208 (stores e = exp(score), unnormalized)
#define OFF_MSK   18000    // 208 (int view)
#define OFF_WRED  18208    // 32 (13 warp partial sums used)
#define OFF_RED   18240    // 1024 -> 19264
#define OFF_WHPB  19264    // 4096 (bf16x2 (Wh,Wp), [n*64+k])
#define OFF_WQB   23360    // 2048 (bf16 Wq [k][n])
#define SMEM_B_FLOATS 25408
#define SMEM_B_BYTES  (SMEM_B_FLOATS * 4)

__global__ __launch_bounds__(512, 2) void din_main(
    const int* __restrict__ hist_id,
    const int* __restrict__ mask,        // bool promoted to 4-byte; test != 0
    const float* __restrict__ table,
    const int* __restrict__ target,
    const float* __restrict__ aw1,
    const float* __restrict__ ab1,
    const float* __restrict__ aw2,
    const float* __restrict__ ab2,
    const float* __restrict__ aow,
    const float* __restrict__ aob) {
    extern __shared__ float sm[];
    unsigned int* smu = (unsigned int*)sm;
    int* smi = (int*)sm;
    unsigned int* whpb = smu + OFF_WHPB;
    __nv_bfloat16* wqb = (__nv_bfloat16*)(smu + OFF_WQB);
    const int tid = threadIdx.x;
    const int w   = tid >> 5;
    const int l   = tid & 31;
    const int l4  = l >> 2;   // 0..7
    const int lm  = l & 3;    // 0..3

    // ---- loop-invariant staging (once per CTA) ----
    if (tid < 32)        sm[OFF_AB2 + tid]      = ab2[tid];
    else if (tid < 64)   sm[OFF_AOW + tid - 32] = aow[tid - 32];
    for (int idx = tid; idx < 32 * 32; idx += 512) {
        int kp = idx & 31, n = idx >> 5;
        float v0 = aw2[(2 * kp) * 32 + n];
        float v1 = aw2[(2 * kp + 1) * 32 + n];
        smu[OFF_W2B + n * PWB + kp] = pack_bf16(v0, v1);
    }
    for (int idx = tid; idx < 64 * 64; idx += 512) {
        int k = idx & 63, n = idx >> 6;
        float a = aw1[k * 64 + n];
        float bb = aw1[(64 + k) * 64 + n];
        float c = aw1[(128 + k) * 64 + n];
        float d = aw1[(192 + k) * 64 + n];
        whpb[n * 64 + k] = pack_bf16(a + c, d);   // lo=Wh, hi=Wp
        wqb[k * 64 + n] = __float2bfloat16(bb - c);
    }
    // zero-pad HIST rows 200..207 ONCE
    {
        float4* hist4 = (float4*)(sm + OFF_HIST);
        for (int idx = tid; idx < 8 * 17; idx += 512) {
            int t = 200 + idx / 17, v = idx % 17;
            hist4[t * 17 + v] = make_float4(0.f, 0.f, 0.f, 0.f);
        }
    }
    const float aob0 = aob[0];
    const float ab1v = (tid < 64) ? ab1[tid] : 0.f;

    for (int b = blockIdx.x; b < B_; b += GRID_MAIN) {
        __syncthreads();   // B0: prior iteration fully done

        // --- stage QV + MSK via cp.async (group A) ---
        if (tid < 16) {
            int tgt = target[b];
            cp_async16(smem_u32(sm + OFF_QV + tid * 4),
                       (const float4*)table + (size_t)tgt * 16 + tid);
        } else if (tid < 66) {
            cp_async16(smem_u32(smi + OFF_MSK + (tid - 16) * 4),
                       (const int4*)(mask + (size_t)b * T_) + (tid - 16));
        }
        CP_COMMIT();   // group A (empty for most threads)

        // --- issue hist gather via cp.async (group B) ---
        {
            const float4* tab4 = (const float4*)table;
            float* histb = sm + OFF_HIST;
            for (int idx = tid; idx < T_ * 16; idx += 512) {
                int t = idx >> 4, v = idx & 15;
                cp_async16(smem_u32(histb + t * PH + v * 4),
                           tab4 + (size_t)hist_id[b * T_ + t] * 16 + v);
            }
            CP_COMMIT();   // group B
        }
        CP_WAIT1();        // group A (QV/MSK) landed; gather may be in flight
        __syncthreads();   // B1: QV/MSK visible

        // --- qb partials: all 512 threads, LDS-only Wq (overlaps gather) ---
        {
            int n = tid & 63, kc = tid >> 6;
            float acc = 0.f;
#pragma unroll
            for (int i = 0; i < 8; ++i) {
                int k = kc * 8 + i;
                acc = fmaf(sm[OFF_QV + k], __bfloat162float(wqb[k * 64 + n]), acc);
            }
            sm[OFF_RED + kc * 64 + n] = acc;
        }
        __syncthreads();   // B1.5: partials ready
        if (tid < 64) {
            float acc = ab1v;
#pragma unroll
            for (int kc = 0; kc < 8; ++kc) acc += sm[OFF_RED + kc * 64 + tid];
            sm[OFF_QB + tid] = acc;
        }
        // --- fold Wc[n][k] = Wh + q[k]*Wp -> bf16 pairs (overlaps gather) ---
        for (int idx = tid; idx < 64 * 32; idx += 512) {
            int kp = idx & 31, n = idx >> 5;
            uint2 hp2 = *(const uint2*)(whpb + n * 64 + 2 * kp);
            __nv_bfloat162 h0 = *(__nv_bfloat162*)&hp2.x;
            __nv_bfloat162 h1 = *(__nv_bfloat162*)&hp2.y;
            float f0 = fmaf(sm[OFF_QV + 2 * kp],     __bfloat162float(h0.y),
                            __bfloat162float(h0.x));
            float f1 = fmaf(sm[OFF_QV + 2 * kp + 1], __bfloat162float(h1.y),
                            __bfloat162float(h1.x));
            smu[OFF_WCB + n * PWB + kp] = pack_bf16(f0, f1);
        }
        CP_WAIT0();        // gather landed
        __syncthreads();   // B2: all operands staged

        // ====== fused attention MLP (bf16 k16): warps 0..12, rows [16w,+16) ===
        if (w < 13) {
            const int mt = w;

            unsigned int a[4][4];
            {
                const float* abase = sm + OFF_HIST + (mt * 16 + l4) * PH + 2 * lm;
#pragma unroll
                for (int ks = 0; ks < 4; ++ks) {
                    float2 v00 = *(const float2*)(abase + 16 * ks);
                    float2 v10 = *(const float2*)(abase + 16 * ks + 8 * PH);
                    float2 v01 = *(const float2*)(abase + 16 * ks + 8);
                    float2 v11 = *(const float2*)(abase + 16 * ks + 8 * PH + 8);
                    a[ks][0] = pack_bf16(v00.x, v00.y);
                    a[ks][1] = pack_bf16(v10.x, v10.y);
                    a[ks][2] = pack_bf16(v01.x, v01.y);
                    a[ks][3] = pack_bf16(v11.x, v11.y);
                }
            }

            float d0[4], d1[4], d2[4], d3[4];
#pragma unroll
            for (int nt = 0; nt < 4; ++nt) {
                float bb0 = sm[OFF_AB2 + nt * 8 + 2 * lm];
                float bb1 = sm[OFF_AB2 + nt * 8 + 2 * lm + 1];
                d0[nt] = bb0; d1[nt] = bb1; d2[nt] = bb0; d3[nt] = bb1;
            }

            const unsigned int* wcbw = smu + OFF_WCB + l4 * PWB + lm;
            const unsigned int* w2bw = smu + OFF_W2B + l4 * PWB + lm;

#pragma unroll
            for (int j = 0; j < 4; ++j) {
                unsigned int A2[4];
#pragma unroll
                for (int t2 = 0; t2 < 2; ++t2) {
                    const int kk = 2 * j + t2;
                    float c0 = sm[OFF_QB + kk * 8 + 2 * lm];
                    float c1 = sm[OFF_QB + kk * 8 + 2 * lm + 1];
                    float c2 = c0, c3 = c1;
                    const unsigned int* wb = wcbw + kk * 8 * PWB;
#pragma unroll
                    for (int ks = 0; ks < 4; ++ks) {
                        unsigned int b0 = wb[8 * ks];
                        unsigned int b1 = wb[8 * ks + 4];
                        mma_bf16(c0, c1, c2, c3,
                                 a[ks][0], a[ks][1], a[ks][2], a[ks][3], b0, b1);
                    }
                    A2[2 * t2 + 0] = pack_bf16(fmaxf(c0, 0.f), fmaxf(c1, 0.f));
                    A2[2 * t2 + 1] = pack_bf16(fmaxf(c2, 0.f), fmaxf(c3, 0.f));
                }
                const unsigned int* w2 = w2bw + 8 * j;
#pragma unroll
                for (int nt = 0; nt < 4; ++nt) {
                    unsigned int b0 = w2[nt * 8 * PWB];
                    unsigned int b1 = w2[nt * 8 * PWB + 4];
                    mma_bf16(d0[nt], d1[nt], d2[nt], d3[nt],
                             A2[0], A2[1], A2[2], A2[3], b0, b1);
                }
            }

            // ---- score -> exp (no-max softmax) + warp partial sum ----
            float p01 = 0.f, p23 = 0.f;
#pragma unroll
            for (int nt = 0; nt < 4; ++nt) {
                float w0 = sm[OFF_AOW + nt * 8 + 2 * lm];
                float w1 = sm[OFF_AOW + nt * 8 + 2 * lm + 1];
                p01 = fmaf(fmaxf(d0[nt], 0.f), w0, fmaf(fmaxf(d1[nt], 0.f), w1, p01));
                p23 = fmaf(fmaxf(d2[nt], 0.f), w0, fmaf(fmaxf(d3[nt], 0.f), w1, p23));
            }
            p01 += __shfl_xor_sync(0xffffffffu, p01, 1);
            p01 += __shfl_xor_sync(0xffffffffu, p01, 2);
            p23 += __shfl_xor_sync(0xffffffffu, p23, 1);
            p23 += __shfl_xor_sync(0xffffffffu, p23, 2);
            float e01 = 0.f, e23 = 0.f;
            if (lm == 0) {
                int r0 = mt * 16 + l4;     // always < 200 for mt <= 12
                int r1 = r0 + 8;
                e01 = (smi[OFF_MSK + r0] != 0) ? __expf(p01 + aob0) : 0.f;
                sm[OFF_SC + r0] = e01;
                if (r1 < T_) {
                    e23 = (smi[OFF_MSK + r1] != 0) ? __expf(p23 + aob0) : 0.f;
                    sm[OFF_SC + r1] = e23;
                }
            }
            float esum = e01 + e23;
            esum += __shfl_xor_sync(0xffffffffu, esum, 16);
            esum += __shfl_xor_sync(0xffffffffu, esum, 8);
            esum += __shfl_xor_sync(0xffffffffu, esum, 4);
            esum += __shfl_xor_sync(0xffffffffu, esum, 2);
            esum += __shfl_xor_sync(0xffffffffu, esum, 1);
            if (l == 0) sm[OFF_WRED + w] = esum;
        }
        __syncthreads();   // B3: e-values + warp sums ready

        // ---- interest (float2, 16 warp-groups; normalization folded) ----
        {
            float ss = 0.f;
#pragma unroll
            for (int i = 0; i < 13; ++i) ss += sm[OFF_WRED + i];
            float inv = 1.f / ss;
            int j2 = (tid & 31) * 2, g = w;
            int tb = (g * 200) >> 4, te = ((g + 1) * 200) >> 4;
            float ax = 0.f, ay = 0.f;
            for (int t = tb; t < te; ++t) {
                float wt = sm[OFF_SC + t];
                float2 h = *(const float2*)(sm + OFF_HIST + t * PH + j2);
                ax = fmaf(wt, h.x, ax);
                ay = fmaf(wt, h.y, ay);
            }
            sm[OFF_RED + g * 64 + j2]     = ax * inv;
            sm[OFF_RED + g * 64 + j2 + 1] = ay * inv;
        }
        __syncthreads();   // B6
        if (tid < 64) {
            float iv = 0.f;
#pragma unroll
            for (int g = 0; g < 16; ++g) iv += sm[OFF_RED + g * 64 + tid];
            g_inter[b * 64 + tid] = iv;
        }
    }
}

// ============================================================
// final MLP v5 (unchanged): tf32x2, 16 rows/CTA, grid 256,
// unified 12-chunk cp.async double-buffered weight pipeline.
// ============================================================
#define DR  16
#define FPX 136
#define FPW 264
#define FX    0        // 16*136 = 2176
#define FG1   2176     // 4224 -> 6400
#define FWT0  6400     // 8448 -> 14848
#define FWT1  14848    // 8448 -> 23296
#define FMB1  23296    // 256
#define FMB2  23552    // 128
#define FOW   23680    // 128
#define FRED  23808    // 128
#define FTGT  23936    // 16 (int view)
#define SMEM_F_FLOATS 23952
#define SMEM_F_BYTES  (SMEM_F_FLOATS * 4)

__global__ __launch_bounds__(256, 2) void din_final(
    const int* __restrict__ target,
    const float* __restrict__ table,
    const float* __restrict__ mw1, const float* __restrict__ mb1,
    const float* __restrict__ mw2, const float* __restrict__ mb2,
    const float* __restrict__ ow,  const float* __restrict__ ob,
    float* __restrict__ out) {
    extern __shared__ float sm[];
    int* smi = (int*)sm;
    const int tid = threadIdx.x;
    const int w   = tid >> 5;   // 0..7
    const int l   = tid & 31;
    const int l4  = l >> 2;
    const int lm  = l & 3;
    const int b0  = blockIdx.x * DR;

    if (tid < DR) smi[FTGT + tid] = target[b0 + tid];
    sm[FMB1 + tid] = mb1[tid];
    if (tid < 128) { sm[FMB2 + tid] = mb2[tid]; sm[FOW + tid] = ow[tid]; }
    __syncthreads();

    // ---- X = concat(item, interest), fp32 ----
    {
        const float4* tab4 = (const float4*)table;
        const float4* int4p = (const float4*)g_inter;
        for (int idx = tid; idx < DR * 32; idx += 256) {
            int rr = idx >> 5, v = idx & 31;
            float4 x = (v < 16)
                ? tab4[(size_t)smi[FTGT + rr] * 16 + v]
                : int4p[(size_t)(b0 + rr) * 16 + (v - 16)];
            *(float4*)(sm + FX + rr * FPX + v * 4) = x;
        }
    }

    // ---- issue chunk 0 (mw1 rows 0..32) into FWT0 ----
    {
        const float4* src = (const float4*)mw1;
        float* dst = sm + FWT0;
        for (int idx = tid; idx < 2048; idx += 256) {
            int r = idx >> 6, v = idx & 63;
            cp_async16(smem_u32(dst + r * FPW + v * 4), src + idx);
        }
        CP_COMMIT();
    }

    const int n0w  = w * 32;
    const int n0w2 = w * 16;
    float acc1[16], acc2[8];

    for (int c = 0; c < 12; ++c) {
        CP_WAIT0();
        __syncthreads();   // chunk c visible; prior compute done

        if (c < 11) {
            int nc = c + 1;
            float* dst = sm + ((nc & 1) ? FWT1 : FWT0);
            if (nc < 4) {
                const float4* src = (const float4*)(mw1 + nc * 32 * 256);
                for (int idx = tid; idx < 2048; idx += 256) {
                    int r = idx >> 6, v = idx & 63;
                    cp_async16(smem_u32(dst + r * FPW + v * 4), src + idx);
                }
            } else {
                const float4* src = (const float4*)(mw2 + (nc - 4) * 32 * 128);
                for (int idx = tid; idx < 1024; idx += 256) {
                    int r = idx >> 5, v = idx & 31;
                    cp_async16(smem_u32(dst + r * FPX + v * 4), src + idx);
                }
            }
            CP_COMMIT();
        }

        const float* wt = sm + ((c & 1) ? FWT1 : FWT0);

        if (c == 0) {
#pragma unroll
            for (int nt = 0; nt < 4; ++nt) {
                float bb0 = sm[FMB1 + n0w + nt * 8 + 2 * lm];
                float bb1 = sm[FMB1 + n0w + nt * 8 + 2 * lm + 1];
                acc1[nt * 4 + 0] = bb0; acc1[nt * 4 + 1] = bb1;
                acc1[nt * 4 + 2] = bb0; acc1[nt * 4 + 3] = bb1;
            }
        }
        if (c == 4) {
#pragma unroll
            for (int nt = 0; nt < 2; ++nt) {
                float bb0 = sm[FMB2 + n0w2 + nt * 8 + 2 * lm];
                float bb1 = sm[FMB2 + n0w2 + nt * 8 + 2 * lm + 1];
                acc2[nt * 4 + 0] = bb0; acc2[nt * 4 + 1] = bb1;
                acc2[nt * 4 + 2] = bb0; acc2[nt * 4 + 3] = bb1;
            }
        }

        if (c < 4) {
#pragma unroll
            for (int s = 0; s < 4; ++s) {
                const float* ab = sm + FX + l4 * FPX + c * 32 + s * 8 + lm;
                unsigned int ah0, al0, ah1, al1, ah2, al2, ah3, al3;
                split_tf32(ab[0],           ah0, al0);
                split_tf32(ab[8 * FPX],     ah1, al1);
                split_tf32(ab[4],           ah2, al2);
                split_tf32(ab[8 * FPX + 4], ah3, al3);
#pragma unroll
                for (int nt = 0; nt < 4; ++nt) {
                    float b0f = wt[(s * 8 + lm) * FPW + n0w + nt * 8 + l4];
                    float b1f = wt[(s * 8 + lm + 4) * FPW + n0w + nt * 8 + l4];
                    unsigned int b0h, b0l, b1h, b1l;
                    split_tf32(b0f, b0h, b0l);
                    split_tf32(b1f, b1h, b1l);
                    int base = nt * 4;
                    mma_tf32(acc1[base + 0], acc1[base + 1], acc1[base + 2], acc1[base + 3],
                             ah0, ah1, ah2, ah3, b0h, b1h);
                    mma_tf32(acc1[base + 0], acc1[base + 1], acc1[base + 2], acc1[base + 3],
                             al0, al1, al2, al3, b0h, b1h);
                    mma_tf32(acc1[base + 0], acc1[base + 1], acc1[base + 2], acc1[base + 3],
                             ah0, ah1, ah2, ah3, b0l, b1l);
                }
            }
            if (c == 3) {
#pragma unroll
                for (int nt = 0; nt < 4; ++nt) {
                    int base = nt * 4;
                    int col = n0w + nt * 8 + 2 * lm;
                    *(float2*)(sm + FG1 + l4 * FPW + col) =
                        make_float2(fmaxf(acc1[base + 0], 0.f), fmaxf(acc1[base + 1], 0.f));
                    *(float2*)(sm + FG1 + (l4 + 8) * FPW + col) =
                        make_float2(fmaxf(acc1[base + 2], 0.f), fmaxf(acc1[base + 3], 0.f));
                }
            }
        } else {
            int ck = c - 4;
#pragma unroll
            for (int s = 0; s < 4; ++s) {
                const float* ab = sm + FG1 + l4 * FPW + ck * 32 + s * 8 + lm;
                unsigned int ah0, al0, ah1, al1, ah2, al2, ah3, al3;
                split_tf32(ab[0],           ah0, al0);
                split_tf32(ab[8 * FPW],     ah1, al1);
                split_tf32(ab[4],           ah2, al2);
                split_tf32(ab[8 * FPW + 4], ah3, al3);
#pragma unroll
                for (int nt = 0; nt < 2; ++nt) {
                    float b0f = wt[(s * 8 + lm) * FPX + n0w2 + nt * 8 + l4];
                    float b1f = wt[(s * 8 + lm + 4) * FPX + n0w2 + nt * 8 + l4];
                    unsigned int b0h, b0l, b1h, b1l;
                    split_tf32(b0f, b0h, b0l);
                    split_tf32(b1f, b1h, b1l);
                    int base = nt * 4;
                    mma_tf32(acc2[base + 0], acc2[base + 1], acc2[base + 2], acc2[base + 3],
                             ah0, ah1, ah2, ah3, b0h, b1h);
                    mma_tf32(acc2[base + 0], acc2[base + 1], acc2[base + 2], acc2[base + 3],
                             al0, al1, al2, al3, b0h, b1h);
                    mma_tf32(acc2[base + 0], acc2[base + 1], acc2[base + 2], acc2[base + 3],
                             ah0, ah1, ah2, ah3, b0l, b1l);
                }
            }
        }
    }

    // ---- stage 3: out = relu(acc2) @ ow + ob ----
    float pA = 0.f, pB = 0.f;
#pragma unroll
    for (int nt = 0; nt < 2; ++nt) {
        int base = nt * 4;
        float w0 = sm[FOW + n0w2 + nt * 8 + 2 * lm];
        float w1 = sm[FOW + n0w2 + nt * 8 + 2 * lm + 1];
        pA = fmaf(fmaxf(acc2[base + 0], 0.f), w0,
             fmaf(fmaxf(acc2[base + 1], 0.f), w1, pA));
        pB = fmaf(fmaxf(acc2[base + 2], 0.f), w0,
             fmaf(fmaxf(acc2[base + 3], 0.f), w1, pB));
    }
    pA += __shfl_xor_sync(0xffffffffu, pA, 1);
    pA += __shfl_xor_sync(0xffffffffu, pA, 2);
    pB += __shfl_xor_sync(0xffffffffu, pB, 1);
    pB += __shfl_xor_sync(0xffffffffu, pB, 2);
    if (lm == 0) {
        sm[FRED + w * 16 + l4]     = pA;
        sm[FRED + w * 16 + l4 + 8] = pB;
    }
    __syncthreads();
    if (tid < DR) {
        float p = ob[0];
#pragma unroll
        for (int w8 = 0; w8 < 8; ++w8) p += sm[FRED + w8 * 16 + tid];
        out[b0 + tid] = p;
    }
}

// ============================================================
// launch
// ============================================================
extern "C" void kernel_launch(void* const* d_in, const int* in_sizes, int n_in,
                              void* d_out, int out_size) {
    const int*   target  = (const int*)d_in[0];
    const int*   hist_id = (const int*)d_in[1];
    const int*   mask    = (const int*)d_in[2];     // bool promoted; test != 0
    const float* table   = (const float*)d_in[3];
    const float* aw1     = (const float*)d_in[4];
    const float* ab1     = (const float*)d_in[5];
    const float* aw2     = (const float*)d_in[6];
    const float* ab2     = (const float*)d_in[7];
    const float* aow     = (const float*)d_in[8];
    const float* aob     = (const float*)d_in[9];
    const float* mw1     = (const float*)d_in[10];
    const float* mb1     = (const float*)d_in[11];
    const float* mw2     = (const float*)d_in[12];
    const float* mb2     = (const float*)d_in[13];
    const float* ow      = (const float*)d_in[14];
    const float* ob      = (const float*)d_in[15];
    float* out = (float*)d_out;

    cudaFuncSetAttribute(din_main, cudaFuncAttributeMaxDynamicSharedMemorySize, SMEM_B_BYTES);
    cudaFuncSetAttribute(din_final, cudaFuncAttributeMaxDynamicSharedMemorySize, SMEM_F_BYTES);

    din_main<<<GRID_MAIN, 512, SMEM_B_BYTES>>>(hist_id, mask, table, target, aw1,
                                               ab1, aw2, ab2, aow, aob);
    din_final<<<B_ / DR, 256, SMEM_F_BYTES>>>(target, table, mw1, mb1,
                                              mw2, mb2, ow, ob, out);
}

// round 14
// speedup vs baseline: 1.3336x; 1.0123x over previous
#include <cuda_runtime.h>
#include <cuda_bf16.h>
#include <math.h>
#include <stdint.h>

// Problem constants
#define B_  4096
#define T_  200
#define E_  64
#define A1_ 64
#define A2_ 32
#define M1_ 256
#define M2_ 128
#define GRID_MAIN 296   // 2 CTAs per SM x 148 SMs

// -------- device scratch (no allocations allowed) --------
__device__ float g_inter[B_ * 64]; // interest vectors

// ---- tf32 helpers (din_final) ----
__device__ __forceinline__ unsigned int f2tf(float f) {
    unsigned int r;
    asm("cvt.rna.tf32.f32 %0, %1;" : "=r"(r) : "f"(f));
    return r;
}
__device__ __forceinline__ void split_tf32(float x, unsigned int& hi, unsigned int& lo) {
    hi = f2tf(x);
    lo = f2tf(x - __uint_as_float(hi));
}
__device__ __forceinline__ void mma_tf32(
    float& c0, float& c1, float& c2, float& c3,
    unsigned int a0, unsigned int a1, unsigned int a2, unsigned int a3,
    unsigned int b0, unsigned int b1) {
    asm("mma.sync.aligned.m16n8k8.row.col.f32.tf32.tf32.f32 "
        "{%0,%1,%2,%3},{%4,%5,%6,%7},{%8,%9},{%0,%1,%2,%3};"
        : "+f"(c0), "+f"(c1), "+f"(c2), "+f"(c3)
        : "r"(a0), "r"(a1), "r"(a2), "r"(a3), "r"(b0), "r"(b1));
}
// ---- bf16 helpers (din_main) ----
__device__ __forceinline__ unsigned int pack_bf16(float lo, float hi) {
    unsigned int r;   // d = {hi, lo}
    asm("cvt.rn.bf16x2.f32 %0, %1, %2;" : "=r"(r) : "f"(hi), "f"(lo));
    return r;
}
__device__ __forceinline__ void mma_bf16(
    float& c0, float& c1, float& c2, float& c3,
    unsigned int a0, unsigned int a1, unsigned int a2, unsigned int a3,
    unsigned int b0, unsigned int b1) {
    asm("mma.sync.aligned.m16n8k16.row.col.f32.bf16.bf16.f32 "
        "{%0,%1,%2,%3},{%4,%5,%6,%7},{%8,%9},{%0,%1,%2,%3};"
        : "+f"(c0), "+f"(c1), "+f"(c2), "+f"(c3)
        : "r"(a0), "r"(a1), "r"(a2), "r"(a3), "r"(b0), "r"(b1));
}
// ---- cp.async helpers ----
__device__ __forceinline__ void cp_async16(unsigned int dst, const void* src) {
    asm volatile("cp.async.ca.shared.global [%0], [%1], 16;" :: "r"(dst), "l"(src) : "memory");
}
__device__ __forceinline__ void cp_async4(unsigned int dst, const void* src) {
    asm volatile("cp.async.ca.shared.global [%0], [%1], 4;" :: "r"(dst), "l"(src) : "memory");
}
__device__ __forceinline__ unsigned int smem_u32(const void* p) {
    return (unsigned int)__cvta_generic_to_shared(p);
}
#define CP_COMMIT() asm volatile("cp.async.commit_group;" ::: "memory")
#define CP_WAIT0()  asm volatile("cp.async.wait_group 0;" ::: "memory")
#define CP_WAIT2()  asm volatile("cp.async.wait_group 2;" ::: "memory")

// ============================================================
// main kernel: PERSISTENT, 296 CTAs x 512 threads, 2 CTAs/SM.
// bf16 k16 attention MLP; ID prefetch pipeline; progressive
// split gather with named barriers; fused exp-softmax epilogue.
// ============================================================
#define PH  68   // HIST pitch (fp32 words)
#define PWB 36   // WCB/W2B pitch (32-bit words)
// smem layout (float/word offsets)
#define OFF_HIST  0        // 208*68 = 14144
#define OFF_WCB   14144    // 2304 -> 16448
#define OFF_W2B   16448    // 1152 -> 17600
#define OFF_QV    17600    // 64
#define OFF_QB    17664    // 64
#define OFF_AB2   17728    // 32
#define OFF_AOW   17760    // 32
#define OFF_SC    17792    // 208 (e = exp(score), unnormalized)
#define OFF_MSK   18000    // 208 (int view)
#define OFF_WRED  18208    // 32 (13 warp partial sums used)
#define OFF_RED   18240    // 1024 -> 19264
#define OFF_WHPB  19264    // 4096 (bf16x2 (Wh,Wp), [n*64+k])
#define OFF_WQB   23360    // 2048 (bf16 Wq [k][n])
#define OFF_NID   25408    // 208 ints (next-iter hist ids)
#define OFF_NTGT  25616    // 1 int (next-iter target), 16B-padded
#define SMEM_B_FLOATS 25632
#define SMEM_B_BYTES  (SMEM_B_FLOATS * 4)

__global__ __launch_bounds__(512, 2) void din_main(
    const int* __restrict__ hist_id,
    const int* __restrict__ mask,        // bool promoted to 4-byte; test != 0
    const float* __restrict__ table,
    const int* __restrict__ target,
    const float* __restrict__ aw1,
    const float* __restrict__ ab1,
    const float* __restrict__ aw2,
    const float* __restrict__ ab2,
    const float* __restrict__ aow,
    const float* __restrict__ aob) {
    extern __shared__ float sm[];
    unsigned int* smu = (unsigned int*)sm;
    int* smi = (int*)sm;
    unsigned int* whpb = smu + OFF_WHPB;
    __nv_bfloat16* wqb = (__nv_bfloat16*)(smu + OFF_WQB);
    const int tid = threadIdx.x;
    const int w   = tid >> 5;
    const int l   = tid & 31;
    const int l4  = l >> 2;   // 0..7
    const int lm  = l & 3;    // 0..3

    // ---- loop-invariant staging (once per CTA) ----
    if (tid < 32)        sm[OFF_AB2 + tid]      = ab2[tid];
    else if (tid < 64)   sm[OFF_AOW + tid - 32] = aow[tid - 32];
    for (int idx = tid; idx < 32 * 32; idx += 512) {
        int kp = idx & 31, n = idx >> 5;
        float v0 = aw2[(2 * kp) * 32 + n];
        float v1 = aw2[(2 * kp + 1) * 32 + n];
        smu[OFF_W2B + n * PWB + kp] = pack_bf16(v0, v1);
    }
    for (int idx = tid; idx < 64 * 64; idx += 512) {
        int k = idx & 63, n = idx >> 6;
        float a = aw1[k * 64 + n];
        float bb = aw1[(64 + k) * 64 + n];
        float c = aw1[(128 + k) * 64 + n];
        float d = aw1[(192 + k) * 64 + n];
        whpb[n * 64 + k] = pack_bf16(a + c, d);   // lo=Wh, hi=Wp
        wqb[k * 64 + n] = __float2bfloat16(bb - c);
    }
    // zero-pad HIST rows 200..207 ONCE
    {
        float4* hist4 = (float4*)(sm + OFF_HIST);
        for (int idx = tid; idx < 8 * 17; idx += 512) {
            int t = 200 + idx / 17, v = idx % 17;
            hist4[t * 17 + v] = make_float4(0.f, 0.f, 0.f, 0.f);
        }
    }
    // first-iteration IDs + target (plain loads; published at B0)
    if (tid < 200) smi[OFF_NID + tid] = hist_id[(size_t)blockIdx.x * T_ + tid];
    if (tid == 256) smi[OFF_NTGT] = target[blockIdx.x];
    const float aob0 = aob[0];
    const float ab1v = (tid < 64) ? ab1[tid] : 0.f;

    for (int b = blockIdx.x; b < B_; b += GRID_MAIN) {
        CP_WAIT0();        // ID prefetch (P) landed (own ops)
        __syncthreads();   // B0: NID/NTGT visible; prior iteration done

        // --- group A: QV (target from smem) + MSK ---
        if (tid < 16) {
            int tgt = smi[OFF_NTGT];
            cp_async16(smem_u32(sm + OFF_QV + tid * 4),
                       (const float4*)table + (size_t)tgt * 16 + tid);
        } else if (tid < 66) {
            cp_async16(smem_u32(smi + OFF_MSK + (tid - 16) * 4),
                       (const int4*)(mask + (size_t)b * T_) + (tid - 16));
        }
        CP_COMMIT();   // A

        // --- group G1: rows 0..111, warps 0..6 (IDs from smem) ---
        if (w < 7) {
            const float4* tab4 = (const float4*)table;
#pragma unroll
            for (int i = 0; i < 8; ++i) {
                int idx = tid + i * 224;
                int t = idx >> 4, v = idx & 15;
                cp_async16(smem_u32(sm + OFF_HIST + t * PH + v * 4),
                           tab4 + (size_t)smi[OFF_NID + t] * 16 + v);
            }
        }
        CP_COMMIT();   // G1
        // --- group G2: rows 112..199, warps 7..15 ---
        if (w >= 7) {
            const float4* tab4 = (const float4*)table;
            int t2 = tid - 224;
            for (int idx2 = t2; idx2 < 1408; idx2 += 288) {
                int t = 112 + (idx2 >> 4), v = idx2 & 15;
                cp_async16(smem_u32(sm + OFF_HIST + t * PH + v * 4),
                           tab4 + (size_t)smi[OFF_NID + t] * 16 + v);
            }
        }
        CP_COMMIT();   // G2
        CP_WAIT2();        // A done
        __syncthreads();   // B1: QV/MSK visible

        // --- qb partials: all 512 threads, LDS-only Wq (overlaps gather) ---
        {
            int n = tid & 63, kc = tid >> 6;
            float acc = 0.f;
#pragma unroll
            for (int i = 0; i < 8; ++i) {
                int k = kc * 8 + i;
                acc = fmaf(sm[OFF_QV + k], __bfloat162float(wqb[k * 64 + n]), acc);
            }
            sm[OFF_RED + kc * 64 + n] = acc;
        }
        __syncthreads();   // B1.5: partials ready
        if (tid < 64) {
            float acc = ab1v;
#pragma unroll
            for (int kc = 0; kc < 8; ++kc) acc += sm[OFF_RED + kc * 64 + tid];
            sm[OFF_QB + tid] = acc;
        }
        // --- fold Wc[n][k] = Wh + q[k]*Wp -> bf16 pairs (overlaps gather) ---
        for (int idx = tid; idx < 64 * 32; idx += 512) {
            int kp = idx & 31, n = idx >> 5;
            uint2 hp2 = *(const uint2*)(whpb + n * 64 + 2 * kp);
            __nv_bfloat162 h0 = *(__nv_bfloat162*)&hp2.x;
            __nv_bfloat162 h1 = *(__nv_bfloat162*)&hp2.y;
            float f0 = fmaf(sm[OFF_QV + 2 * kp],     __bfloat162float(h0.y),
                            __bfloat162float(h0.x));
            float f1 = fmaf(sm[OFF_QV + 2 * kp + 1], __bfloat162float(h1.y),
                            __bfloat162float(h1.x));
            smu[OFF_WCB + n * PWB + kp] = pack_bf16(f0, f1);
        }
        __syncthreads();   // B2: QB/WCB visible (gather may still be in flight)

        // --- progressive gather publication ---
        if (w < 7) {
            CP_WAIT0();    // own G1 ops done (G2 empty)
            asm volatile("bar.sync 2, 224;" ::: "memory");      // rows 0..111 visible
        } else if (w < 13) {
            CP_WAIT0();    // own G2 ops done
            asm volatile("bar.sync 1, 288;" ::: "memory");      // rows 112..199 visible
        } else {
            CP_WAIT0();
            asm volatile("bar.arrive 1, 288;" ::: "memory");
        }

        // ====== fused attention MLP (bf16 k16): warps 0..12, rows [16w,+16) ===
        if (w < 13) {
            const int mt = w;

            unsigned int a[4][4];
            {
                const float* abase = sm + OFF_HIST + (mt * 16 + l4) * PH + 2 * lm;
#pragma unroll
                for (int ks = 0; ks < 4; ++ks) {
                    float2 v00 = *(const float2*)(abase + 16 * ks);
                    float2 v10 = *(const float2*)(abase + 16 * ks + 8 * PH);
                    float2 v01 = *(const float2*)(abase + 16 * ks + 8);
                    float2 v11 = *(const float2*)(abase + 16 * ks + 8 * PH + 8);
                    a[ks][0] = pack_bf16(v00.x, v00.y);
                    a[ks][1] = pack_bf16(v10.x, v10.y);
                    a[ks][2] = pack_bf16(v01.x, v01.y);
                    a[ks][3] = pack_bf16(v11.x, v11.y);
                }
            }

            float d0[4], d1[4], d2[4], d3[4];
#pragma unroll
            for (int nt = 0; nt < 4; ++nt) {
                float bb0 = sm[OFF_AB2 + nt * 8 + 2 * lm];
                float bb1 = sm[OFF_AB2 + nt * 8 + 2 * lm + 1];
                d0[nt] = bb0; d1[nt] = bb1; d2[nt] = bb0; d3[nt] = bb1;
            }

            const unsigned int* wcbw = smu + OFF_WCB + l4 * PWB + lm;
            const unsigned int* w2bw = smu + OFF_W2B + l4 * PWB + lm;

#pragma unroll
            for (int j = 0; j < 4; ++j) {
                unsigned int A2[4];
#pragma unroll
                for (int t2 = 0; t2 < 2; ++t2) {
                    const int kk = 2 * j + t2;
                    float c0 = sm[OFF_QB + kk * 8 + 2 * lm];
                    float c1 = sm[OFF_QB + kk * 8 + 2 * lm + 1];
                    float c2 = c0, c3 = c1;
                    const unsigned int* wb = wcbw + kk * 8 * PWB;
#pragma unroll
                    for (int ks = 0; ks < 4; ++ks) {
                        unsigned int b0 = wb[8 * ks];
                        unsigned int b1 = wb[8 * ks + 4];
                        mma_bf16(c0, c1, c2, c3,
                                 a[ks][0], a[ks][1], a[ks][2], a[ks][3], b0, b1);
                    }
                    A2[2 * t2 + 0] = pack_bf16(fmaxf(c0, 0.f), fmaxf(c1, 0.f));
                    A2[2 * t2 + 1] = pack_bf16(fmaxf(c2, 0.f), fmaxf(c3, 0.f));
                }
                const unsigned int* w2 = w2bw + 8 * j;
#pragma unroll
                for (int nt = 0; nt < 4; ++nt) {
                    unsigned int b0 = w2[nt * 8 * PWB];
                    unsigned int b1 = w2[nt * 8 * PWB + 4];
                    mma_bf16(d0[nt], d1[nt], d2[nt], d3[nt],
                             A2[0], A2[1], A2[2], A2[3], b0, b1);
                }
            }

            // ---- score -> exp (no-max softmax) + warp partial sum ----
            float p01 = 0.f, p23 = 0.f;
#pragma unroll
            for (int nt = 0; nt < 4; ++nt) {
                float w0 = sm[OFF_AOW + nt * 8 + 2 * lm];
                float w1 = sm[OFF_AOW + nt * 8 + 2 * lm + 1];
                p01 = fmaf(fmaxf(d0[nt], 0.f), w0, fmaf(fmaxf(d1[nt], 0.f), w1, p01));
                p23 = fmaf(fmaxf(d2[nt], 0.f), w0, fmaf(fmaxf(d3[nt], 0.f), w1, p23));
            }
            p01 += __shfl_xor_sync(0xffffffffu, p01, 1);
            p01 += __shfl_xor_sync(0xffffffffu, p01, 2);
            p23 += __shfl_xor_sync(0xffffffffu, p23, 1);
            p23 += __shfl_xor_sync(0xffffffffu, p23, 2);
            float e01 = 0.f, e23 = 0.f;
            if (lm == 0) {
                int r0 = mt * 16 + l4;
                int r1 = r0 + 8;
                e01 = (smi[OFF_MSK + r0] != 0) ? __expf(p01 + aob0) : 0.f;
                sm[OFF_SC + r0] = e01;
                if (r1 < T_) {
                    e23 = (smi[OFF_MSK + r1] != 0) ? __expf(p23 + aob0) : 0.f;
                    sm[OFF_SC + r1] = e23;
                }
            }
            float esum = e01 + e23;
            esum += __shfl_xor_sync(0xffffffffu, esum, 16);
            esum += __shfl_xor_sync(0xffffffffu, esum, 8);
            esum += __shfl_xor_sync(0xffffffffu, esum, 4);
            esum += __shfl_xor_sync(0xffffffffu, esum, 2);
            esum += __shfl_xor_sync(0xffffffffu, esum, 1);
            if (l == 0) sm[OFF_WRED + w] = esum;
        }
        __syncthreads();   // B3: e-values + warp sums ready

        // --- prefetch next-iter IDs + target (group P; lands during epilogue) ---
        {
            int nb = b + GRID_MAIN;
            if (nb < B_) {
                if (tid < 50)
                    cp_async16(smem_u32(smi + OFF_NID + tid * 4),
                               (const int4*)(hist_id + (size_t)nb * T_) + tid);
                else if (tid == 50)
                    cp_async4(smem_u32(smi + OFF_NTGT), target + nb);
            }
            CP_COMMIT();   // P
        }

        // ---- interest (float2, 16 warp-groups; normalization folded) ----
        {
            float ss = 0.f;
#pragma unroll
            for (int i = 0; i < 13; ++i) ss += sm[OFF_WRED + i];
            float inv = 1.f / ss;
            int j2 = (tid & 31) * 2, g = w;
            int tb = (g * 200) >> 4, te = ((g + 1) * 200) >> 4;
            float ax = 0.f, ay = 0.f;
            for (int t = tb; t < te; ++t) {
                float wt = sm[OFF_SC + t];
                float2 h = *(const float2*)(sm + OFF_HIST + t * PH + j2);
                ax = fmaf(wt, h.x, ax);
                ay = fmaf(wt, h.y, ay);
            }
            sm[OFF_RED + g * 64 + j2]     = ax * inv;
            sm[OFF_RED + g * 64 + j2 + 1] = ay * inv;
        }
        __syncthreads();   // B6
        if (tid < 64) {
            float iv = 0.f;
#pragma unroll
            for (int g = 0; g < 16; ++g) iv += sm[OFF_RED + g * 64 + tid];
            g_inter[b * 64 + tid] = iv;
        }
    }
}

// ============================================================
// final MLP v5 (unchanged): tf32x2, 16 rows/CTA, grid 256,
// unified 12-chunk cp.async double-buffered weight pipeline.
// ============================================================
#define DR  16
#define FPX 136
#define FPW 264
#define FX    0        // 16*136 = 2176
#define FG1   2176     // 4224 -> 6400
#define FWT0  6400     // 8448 -> 14848
#define FWT1  14848    // 8448 -> 23296
#define FMB1  23296    // 256
#define FMB2  23552    // 128
#define FOW   23680    // 128
#define FRED  23808    // 128
#define FTGT  23936    // 16 (int view)
#define SMEM_F_FLOATS 23952
#define SMEM_F_BYTES  (SMEM_F_FLOATS * 4)

__global__ __launch_bounds__(256, 2) void din_final(
    const int* __restrict__ target,
    const float* __restrict__ table,
    const float* __restrict__ mw1, const float* __restrict__ mb1,
    const float* __restrict__ mw2, const float* __restrict__ mb2,
    const float* __restrict__ ow,  const float* __restrict__ ob,
    float* __restrict__ out) {
    extern __shared__ float sm[];
    int* smi = (int*)sm;
    const int tid = threadIdx.x;
    const int w   = tid >> 5;   // 0..7
    const int l   = tid & 31;
    const int l4  = l >> 2;
    const int lm  = l & 3;
    const int b0  = blockIdx.x * DR;

    if (tid < DR) smi[FTGT + tid] = target[b0 + tid];
    sm[FMB1 + tid] = mb1[tid];
    if (tid < 128) { sm[FMB2 + tid] = mb2[tid]; sm[FOW + tid] = ow[tid]; }
    __syncthreads();

    {
        const float4* tab4 = (const float4*)table;
        const float4* int4p = (const float4*)g_inter;
        for (int idx = tid; idx < DR * 32; idx += 256) {
            int rr = idx >> 5, v = idx & 31;
            float4 x = (v < 16)
                ? tab4[(size_t)smi[FTGT + rr] * 16 + v]
                : int4p[(size_t)(b0 + rr) * 16 + (v - 16)];
            *(float4*)(sm + FX + rr * FPX + v * 4) = x;
        }
    }

    {
        const float4* src = (const float4*)mw1;
        float* dst = sm + FWT0;
        for (int idx = tid; idx < 2048; idx += 256) {
            int r = idx >> 6, v = idx & 63;
            cp_async16(smem_u32(dst + r * FPW + v * 4), src + idx);
        }
        CP_COMMIT();
    }

    const int n0w  = w * 32;
    const int n0w2 = w * 16;
    float acc1[16], acc2[8];

    for (int c = 0; c < 12; ++c) {
        CP_WAIT0();
        __syncthreads();

        if (c < 11) {
            int nc = c + 1;
            float* dst = sm + ((nc & 1) ? FWT1 : FWT0);
            if (nc < 4) {
                const float4* src = (const float4*)(mw1 + nc * 32 * 256);
                for (int idx = tid; idx < 2048; idx += 256) {
                    int r = idx >> 6, v = idx & 63;
                    cp_async16(smem_u32(dst + r * FPW + v * 4), src + idx);
                }
            } else {
                const float4* src = (const float4*)(mw2 + (nc - 4) * 32 * 128);
                for (int idx = tid; idx < 1024; idx += 256) {
                    int r = idx >> 5, v = idx & 31;
                    cp_async16(smem_u32(dst + r * FPX + v * 4), src + idx);
                }
            }
            CP_COMMIT();
        }

        const float* wt = sm + ((c & 1) ? FWT1 : FWT0);

        if (c == 0) {
#pragma unroll
            for (int nt = 0; nt < 4; ++nt) {
                float bb0 = sm[FMB1 + n0w + nt * 8 + 2 * lm];
                float bb1 = sm[FMB1 + n0w + nt * 8 + 2 * lm + 1];
                acc1[nt * 4 + 0] = bb0; acc1[nt * 4 + 1] = bb1;
                acc1[nt * 4 + 2] = bb0; acc1[nt * 4 + 3] = bb1;
            }
        }
        if (c == 4) {
#pragma unroll
            for (int nt = 0; nt < 2; ++nt) {
                float bb0 = sm[FMB2 + n0w2 + nt * 8 + 2 * lm];
                float bb1 = sm[FMB2 + n0w2 + nt * 8 + 2 * lm + 1];
                acc2[nt * 4 + 0] = bb0; acc2[nt * 4 + 1] = bb1;
                acc2[nt * 4 + 2] = bb0; acc2[nt * 4 + 3] = bb1;
            }
        }

        if (c < 4) {
#pragma unroll
            for (int s = 0; s < 4; ++s) {
                const float* ab = sm + FX + l4 * FPX + c * 32 + s * 8 + lm;
                unsigned int ah0, al0, ah1, al1, ah2, al2, ah3, al3;
                split_tf32(ab[0],           ah0, al0);
                split_tf32(ab[8 * FPX],     ah1, al1);
                split_tf32(ab[4],           ah2, al2);
                split_tf32(ab[8 * FPX + 4], ah3, al3);
#pragma unroll
                for (int nt = 0; nt < 4; ++nt) {
                    float b0f = wt[(s * 8 + lm) * FPW + n0w + nt * 8 + l4];
                    float b1f = wt[(s * 8 + lm + 4) * FPW + n0w + nt * 8 + l4];
                    unsigned int b0h, b0l, b1h, b1l;
                    split_tf32(b0f, b0h, b0l);
                    split_tf32(b1f, b1h, b1l);
                    int base = nt * 4;
                    mma_tf32(acc1[base + 0], acc1[base + 1], acc1[base + 2], acc1[base + 3],
                             ah0, ah1, ah2, ah3, b0h, b1h);
                    mma_tf32(acc1[base + 0], acc1[base + 1], acc1[base + 2], acc1[base + 3],
                             al0, al1, al2, al3, b0h, b1h);
                    mma_tf32(acc1[base + 0], acc1[base + 1], acc1[base + 2], acc1[base + 3],
                             ah0, ah1, ah2, ah3, b0l, b1l);
                }
            }
            if (c == 3) {
#pragma unroll
                for (int nt = 0; nt < 4; ++nt) {
                    int base = nt * 4;
                    int col = n0w + nt * 8 + 2 * lm;
                    *(float2*)(sm + FG1 + l4 * FPW + col) =
                        make_float2(fmaxf(acc1[base + 0], 0.f), fmaxf(acc1[base + 1], 0.f));
                    *(float2*)(sm + FG1 + (l4 + 8) * FPW + col) =
                        make_float2(fmaxf(acc1[base + 2], 0.f), fmaxf(acc1[base + 3], 0.f));
                }
            }
        } else {
            int ck = c - 4;
#pragma unroll
            for (int s = 0; s < 4; ++s) {
                const float* ab = sm + FG1 + l4 * FPW + ck * 32 + s * 8 + lm;
                unsigned int ah0, al0, ah1, al1, ah2, al2, ah3, al3;
                split_tf32(ab[0],           ah0, al0);
                split_tf32(ab[8 * FPW],     ah1, al1);
                split_tf32(ab[4],           ah2, al2);
                split_tf32(ab[8 * FPW + 4], ah3, al3);
#pragma unroll
                for (int nt = 0; nt < 2; ++nt) {
                    float b0f = wt[(s * 8 + lm) * FPX + n0w2 + nt * 8 + l4];
                    float b1f = wt[(s * 8 + lm + 4) * FPX + n0w2 + nt * 8 + l4];
                    unsigned int b0h, b0l, b1h, b1l;
                    split_tf32(b0f, b0h, b0l);
                    split_tf32(b1f, b1h, b1l);
                    int base = nt * 4;
                    mma_tf32(acc2[base + 0], acc2[base + 1], acc2[base + 2], acc2[base + 3],
                             ah0, ah1, ah2, ah3, b0h, b1h);
                    mma_tf32(acc2[base + 0], acc2[base + 1], acc2[base + 2], acc2[base + 3],
                             al0, al1, al2, al3, b0h, b1h);
                    mma_tf32(acc2[base + 0], acc2[base + 1], acc2[base + 2], acc2[base + 3],
                             ah0, ah1, ah2, ah3, b0l, b1l);
                }
            }
        }
    }

    float pA = 0.f, pB = 0.f;
#pragma unroll
    for (int nt = 0; nt < 2; ++nt) {
        int base = nt * 4;
        float w0 = sm[FOW + n0w2 + nt * 8 + 2 * lm];
        float w1 = sm[FOW + n0w2 + nt * 8 + 2 * lm + 1];
        pA = fmaf(fmaxf(acc2[base + 0], 0.f), w0,
             fmaf(fmaxf(acc2[base + 1], 0.f), w1, pA));
        pB = fmaf(fmaxf(acc2[base + 2], 0.f), w0,
             fmaf(fmaxf(acc2[base + 3], 0.f), w1, pB));
    }
    pA += __shfl_xor_sync(0xffffffffu, pA, 1);
    pA += __shfl_xor_sync(0xffffffffu, pA, 2);
    pB += __shfl_xor_sync(0xffffffffu, pB, 1);
    pB += __shfl_xor_sync(0xffffffffu, pB, 2);
    if (lm == 0) {
        sm[FRED + w * 16 + l4]     = pA;
        sm[FRED + w * 16 + l4 + 8] = pB;
    }
    __syncthreads();
    if (tid < DR) {
        float p = ob[0];
#pragma unroll
        for (int w8 = 0; w8 < 8; ++w8) p += sm[FRED + w8 * 16 + tid];
        out[b0 + tid] = p;
    }
}

// ============================================================
// launch
// ============================================================
extern "C" void kernel_launch(void* const* d_in, const int* in_sizes, int n_in,
                              void* d_out, int out_size) {
    const int*   target  = (const int*)d_in[0];
    const int*   hist_id = (const int*)d_in[1];
    const int*   mask    = (const int*)d_in[2];     // bool promoted; test != 0
    const float* table   = (const float*)d_in[3];
    const float* aw1     = (const float*)d_in[4];
    const float* ab1     = (const float*)d_in[5];
    const float* aw2     = (const float*)d_in[6];
    const float* ab2     = (const float*)d_in[7];
    const float* aow     = (const float*)d_in[8];
    const float* aob     = (const float*)d_in[9];
    const float* mw1     = (const float*)d_in[10];
    const float* mb1     = (const float*)d_in[11];
    const float* mw2     = (const float*)d_in[12];
    const float* mb2     = (const float*)d_in[13];
    const float* ow      = (const float*)d_in[14];
    const float* ob      = (const float*)d_in[15];
    float* out = (float*)d_out;

    cudaFuncSetAttribute(din_main, cudaFuncAttributeMaxDynamicSharedMemorySize, SMEM_B_BYTES);
    cudaFuncSetAttribute(din_final, cudaFuncAttributeMaxDynamicSharedMemorySize, SMEM_F_BYTES);

    din_main<<<GRID_MAIN, 512, SMEM_B_BYTES>>>(hist_id, mask, table, target, aw1,
                                               ab1, aw2, ab2, aow, aob);
    din_final<<<B_ / DR, 256, SMEM_F_BYTES>>>(target, table, mw1, mb1,
                                              mw2, mb2, ow, ob, out);
}

// round 15
// speedup vs baseline: 1.3985x; 1.0487x over previous
#include <cuda_runtime.h>
#include <cuda_bf16.h>
#include <math.h>
#include <stdint.h>

// Problem constants
#define B_  4096
#define T_  200
#define E_  64
#define A1_ 64
#define A2_ 32
#define M1_ 256
#define M2_ 128
#define GRID_MAIN 296   // 2 CTAs per SM x 148 SMs

// -------- device scratch (no allocations allowed) --------
__device__ float g_inter[B_ * 64];        // interest vectors
__device__ unsigned int g_w1hi[64 * 256]; // mw1 bf16-pair hi plane [kpair][n]
__device__ unsigned int g_w1lo[64 * 256]; // mw1 lo plane
__device__ unsigned int g_w2hi[128 * 128];// mw2 hi plane
__device__ unsigned int g_w2lo[128 * 128];// mw2 lo plane

// ---- bf16 helpers ----
__device__ __forceinline__ unsigned int pack_bf16(float lo, float hi) {
    unsigned int r;   // d = {hi, lo}
    asm("cvt.rn.bf16x2.f32 %0, %1, %2;" : "=r"(r) : "f"(hi), "f"(lo));
    return r;
}
__device__ __forceinline__ void split2_bf16(float x0, float x1,
                                            unsigned int& hi, unsigned int& lo) {
    hi = pack_bf16(x0, x1);
    float h0 = __bfloat162float(__float2bfloat16(x0));
    float h1 = __bfloat162float(__float2bfloat16(x1));
    lo = pack_bf16(x0 - h0, x1 - h1);
}
__device__ __forceinline__ void mma_bf16(
    float& c0, float& c1, float& c2, float& c3,
    unsigned int a0, unsigned int a1, unsigned int a2, unsigned int a3,
    unsigned int b0, unsigned int b1) {
    asm("mma.sync.aligned.m16n8k16.row.col.f32.bf16.bf16.f32 "
        "{%0,%1,%2,%3},{%4,%5,%6,%7},{%8,%9},{%0,%1,%2,%3};"
        : "+f"(c0), "+f"(c1), "+f"(c2), "+f"(c3)
        : "r"(a0), "r"(a1), "r"(a2), "r"(a3), "r"(b0), "r"(b1));
}
// ---- cp.async helpers ----
__device__ __forceinline__ void cp_async16(unsigned int dst, const void* src) {
    asm volatile("cp.async.ca.shared.global [%0], [%1], 16;" :: "r"(dst), "l"(src) : "memory");
}
__device__ __forceinline__ void cp_async4(unsigned int dst, const void* src) {
    asm volatile("cp.async.ca.shared.global [%0], [%1], 4;" :: "r"(dst), "l"(src) : "memory");
}
__device__ __forceinline__ unsigned int smem_u32(const void* p) {
    return (unsigned int)__cvta_generic_to_shared(p);
}
#define CP_COMMIT() asm volatile("cp.async.commit_group;" ::: "memory")
#define CP_WAIT0()  asm volatile("cp.async.wait_group 0;" ::: "memory")
#define CP_WAIT2()  asm volatile("cp.async.wait_group 2;" ::: "memory")

// ============================================================
// prep kernels: offline bf16x2 split of mw1 / mw2 into hi/lo
// packed-pair planes [kpair][n].
// ============================================================
__global__ void prep_w1(const float* __restrict__ mw1) {
    int idx = blockIdx.x * blockDim.x + threadIdx.x;   // 64*256
    int p = idx >> 8, n = idx & 255;
    float x0 = mw1[(2 * p) * 256 + n];
    float x1 = mw1[(2 * p + 1) * 256 + n];
    unsigned int hi, lo;
    split2_bf16(x0, x1, hi, lo);
    g_w1hi[idx] = hi;
    g_w1lo[idx] = lo;
}
__global__ void prep_w2(const float* __restrict__ mw2) {
    int idx = blockIdx.x * blockDim.x + threadIdx.x;   // 128*128
    int p = idx >> 7, n = idx & 127;
    float x0 = mw2[(2 * p) * 128 + n];
    float x1 = mw2[(2 * p + 1) * 128 + n];
    unsigned int hi, lo;
    split2_bf16(x0, x1, hi, lo);
    g_w2hi[idx] = hi;
    g_w2lo[idx] = lo;
}

// ============================================================
// main kernel (UNCHANGED from R14): PERSISTENT, 296x512, 2 CTAs/SM.
// ============================================================
#define PH  68
#define PWB 36
#define OFF_HIST  0
#define OFF_WCB   14144
#define OFF_W2B   16448
#define OFF_QV    17600
#define OFF_QB    17664
#define OFF_AB2   17728
#define OFF_AOW   17760
#define OFF_SC    17792
#define OFF_MSK   18000
#define OFF_WRED  18208
#define OFF_RED   18240
#define OFF_WHPB  19264
#define OFF_WQB   23360
#define OFF_NID   25408
#define OFF_NTGT  25616
#define SMEM_B_FLOATS 25632
#define SMEM_B_BYTES  (SMEM_B_FLOATS * 4)

__global__ __launch_bounds__(512, 2) void din_main(
    const int* __restrict__ hist_id,
    const int* __restrict__ mask,
    const float* __restrict__ table,
    const int* __restrict__ target,
    const float* __restrict__ aw1,
    const float* __restrict__ ab1,
    const float* __restrict__ aw2,
    const float* __restrict__ ab2,
    const float* __restrict__ aow,
    const float* __restrict__ aob) {
    extern __shared__ float sm[];
    unsigned int* smu = (unsigned int*)sm;
    int* smi = (int*)sm;
    unsigned int* whpb = smu + OFF_WHPB;
    __nv_bfloat16* wqb = (__nv_bfloat16*)(smu + OFF_WQB);
    const int tid = threadIdx.x;
    const int w   = tid >> 5;
    const int l   = tid & 31;
    const int l4  = l >> 2;
    const int lm  = l & 3;

    if (tid < 32)        sm[OFF_AB2 + tid]      = ab2[tid];
    else if (tid < 64)   sm[OFF_AOW + tid - 32] = aow[tid - 32];
    for (int idx = tid; idx < 32 * 32; idx += 512) {
        int kp = idx & 31, n = idx >> 5;
        float v0 = aw2[(2 * kp) * 32 + n];
        float v1 = aw2[(2 * kp + 1) * 32 + n];
        smu[OFF_W2B + n * PWB + kp] = pack_bf16(v0, v1);
    }
    for (int idx = tid; idx < 64 * 64; idx += 512) {
        int k = idx & 63, n = idx >> 6;
        float a = aw1[k * 64 + n];
        float bb = aw1[(64 + k) * 64 + n];
        float c = aw1[(128 + k) * 64 + n];
        float d = aw1[(192 + k) * 64 + n];
        whpb[n * 64 + k] = pack_bf16(a + c, d);
        wqb[k * 64 + n] = __float2bfloat16(bb - c);
    }
    {
        float4* hist4 = (float4*)(sm + OFF_HIST);
        for (int idx = tid; idx < 8 * 17; idx += 512) {
            int t = 200 + idx / 17, v = idx % 17;
            hist4[t * 17 + v] = make_float4(0.f, 0.f, 0.f, 0.f);
        }
    }
    if (tid < 200) smi[OFF_NID + tid] = hist_id[(size_t)blockIdx.x * T_ + tid];
    if (tid == 256) smi[OFF_NTGT] = target[blockIdx.x];
    const float aob0 = aob[0];
    const float ab1v = (tid < 64) ? ab1[tid] : 0.f;

    for (int b = blockIdx.x; b < B_; b += GRID_MAIN) {
        CP_WAIT0();
        __syncthreads();   // B0

        if (tid < 16) {
            int tgt = smi[OFF_NTGT];
            cp_async16(smem_u32(sm + OFF_QV + tid * 4),
                       (const float4*)table + (size_t)tgt * 16 + tid);
        } else if (tid < 66) {
            cp_async16(smem_u32(smi + OFF_MSK + (tid - 16) * 4),
                       (const int4*)(mask + (size_t)b * T_) + (tid - 16));
        }
        CP_COMMIT();   // A

        if (w < 7) {
            const float4* tab4 = (const float4*)table;
#pragma unroll
            for (int i = 0; i < 8; ++i) {
                int idx = tid + i * 224;
                int t = idx >> 4, v = idx & 15;
                cp_async16(smem_u32(sm + OFF_HIST + t * PH + v * 4),
                           tab4 + (size_t)smi[OFF_NID + t] * 16 + v);
            }
        }
        CP_COMMIT();   // G1
        if (w >= 7) {
            const float4* tab4 = (const float4*)table;
            int t2 = tid - 224;
            for (int idx2 = t2; idx2 < 1408; idx2 += 288) {
                int t = 112 + (idx2 >> 4), v = idx2 & 15;
                cp_async16(smem_u32(sm + OFF_HIST + t * PH + v * 4),
                           tab4 + (size_t)smi[OFF_NID + t] * 16 + v);
            }
        }
        CP_COMMIT();   // G2
        CP_WAIT2();
        __syncthreads();   // B1

        {
            int n = tid & 63, kc = tid >> 6;
            float acc = 0.f;
#pragma unroll
            for (int i = 0; i < 8; ++i) {
                int k = kc * 8 + i;
                acc = fmaf(sm[OFF_QV + k], __bfloat162float(wqb[k * 64 + n]), acc);
            }
            sm[OFF_RED + kc * 64 + n] = acc;
        }
        __syncthreads();   // B1.5
        if (tid < 64) {
            float acc = ab1v;
#pragma unroll
            for (int kc = 0; kc < 8; ++kc) acc += sm[OFF_RED + kc * 64 + tid];
            sm[OFF_QB + tid] = acc;
        }
        for (int idx = tid; idx < 64 * 32; idx += 512) {
            int kp = idx & 31, n = idx >> 5;
            uint2 hp2 = *(const uint2*)(whpb + n * 64 + 2 * kp);
            __nv_bfloat162 h0 = *(__nv_bfloat162*)&hp2.x;
            __nv_bfloat162 h1 = *(__nv_bfloat162*)&hp2.y;
            float f0 = fmaf(sm[OFF_QV + 2 * kp],     __bfloat162float(h0.y),
                            __bfloat162float(h0.x));
            float f1 = fmaf(sm[OFF_QV + 2 * kp + 1], __bfloat162float(h1.y),
                            __bfloat162float(h1.x));
            smu[OFF_WCB + n * PWB + kp] = pack_bf16(f0, f1);
        }
        __syncthreads();   // B2

        if (w < 7) {
            CP_WAIT0();
            asm volatile("bar.sync 2, 224;" ::: "memory");
        } else if (w < 13) {
            CP_WAIT0();
            asm volatile("bar.sync 1, 288;" ::: "memory");
        } else {
            CP_WAIT0();
            asm volatile("bar.arrive 1, 288;" ::: "memory");
        }

        if (w < 13) {
            const int mt = w;

            unsigned int a[4][4];
            {
                const float* abase = sm + OFF_HIST + (mt * 16 + l4) * PH + 2 * lm;
#pragma unroll
                for (int ks = 0; ks < 4; ++ks) {
                    float2 v00 = *(const float2*)(abase + 16 * ks);
                    float2 v10 = *(const float2*)(abase + 16 * ks + 8 * PH);
                    float2 v01 = *(const float2*)(abase + 16 * ks + 8);
                    float2 v11 = *(const float2*)(abase + 16 * ks + 8 * PH + 8);
                    a[ks][0] = pack_bf16(v00.x, v00.y);
                    a[ks][1] = pack_bf16(v10.x, v10.y);
                    a[ks][2] = pack_bf16(v01.x, v01.y);
                    a[ks][3] = pack_bf16(v11.x, v11.y);
                }
            }

            float d0[4], d1[4], d2[4], d3[4];
#pragma unroll
            for (int nt = 0; nt < 4; ++nt) {
                float bb0 = sm[OFF_AB2 + nt * 8 + 2 * lm];
                float bb1 = sm[OFF_AB2 + nt * 8 + 2 * lm + 1];
                d0[nt] = bb0; d1[nt] = bb1; d2[nt] = bb0; d3[nt] = bb1;
            }

            const unsigned int* wcbw = smu + OFF_WCB + l4 * PWB + lm;
            const unsigned int* w2bw = smu + OFF_W2B + l4 * PWB + lm;

#pragma unroll
            for (int j = 0; j < 4; ++j) {
                unsigned int A2[4];
#pragma unroll
                for (int t2 = 0; t2 < 2; ++t2) {
                    const int kk = 2 * j + t2;
                    float c0 = sm[OFF_QB + kk * 8 + 2 * lm];
                    float c1 = sm[OFF_QB + kk * 8 + 2 * lm + 1];
                    float c2 = c0, c3 = c1;
                    const unsigned int* wb = wcbw + kk * 8 * PWB;
#pragma unroll
                    for (int ks = 0; ks < 4; ++ks) {
                        unsigned int b0 = wb[8 * ks];
                        unsigned int b1 = wb[8 * ks + 4];
                        mma_bf16(c0, c1, c2, c3,
                                 a[ks][0], a[ks][1], a[ks][2], a[ks][3], b0, b1);
                    }
                    A2[2 * t2 + 0] = pack_bf16(fmaxf(c0, 0.f), fmaxf(c1, 0.f));
                    A2[2 * t2 + 1] = pack_bf16(fmaxf(c2, 0.f), fmaxf(c3, 0.f));
                }
                const unsigned int* w2 = w2bw + 8 * j;
#pragma unroll
                for (int nt = 0; nt < 4; ++nt) {
                    unsigned int b0 = w2[nt * 8 * PWB];
                    unsigned int b1 = w2[nt * 8 * PWB + 4];
                    mma_bf16(d0[nt], d1[nt], d2[nt], d3[nt],
                             A2[0], A2[1], A2[2], A2[3], b0, b1);
                }
            }

            float p01 = 0.f, p23 = 0.f;
#pragma unroll
            for (int nt = 0; nt < 4; ++nt) {
                float w0 = sm[OFF_AOW + nt * 8 + 2 * lm];
                float w1 = sm[OFF_AOW + nt * 8 + 2 * lm + 1];
                p01 = fmaf(fmaxf(d0[nt], 0.f), w0, fmaf(fmaxf(d1[nt], 0.f), w1, p01));
                p23 = fmaf(fmaxf(d2[nt], 0.f), w0, fmaf(fmaxf(d3[nt], 0.f), w1, p23));
            }
            p01 += __shfl_xor_sync(0xffffffffu, p01, 1);
            p01 += __shfl_xor_sync(0xffffffffu, p01, 2);
            p23 += __shfl_xor_sync(0xffffffffu, p23, 1);
            p23 += __shfl_xor_sync(0xffffffffu, p23, 2);
            float e01 = 0.f, e23 = 0.f;
            if (lm == 0) {
                int r0 = mt * 16 + l4;
                int r1 = r0 + 8;
                e01 = (smi[OFF_MSK + r0] != 0) ? __expf(p01 + aob0) : 0.f;
                sm[OFF_SC + r0] = e01;
                if (r1 < T_) {
                    e23 = (smi[OFF_MSK + r1] != 0) ? __expf(p23 + aob0) : 0.f;
                    sm[OFF_SC + r1] = e23;
                }
            }
            float esum = e01 + e23;
            esum += __shfl_xor_sync(0xffffffffu, esum, 16);
            esum += __shfl_xor_sync(0xffffffffu, esum, 8);
            esum += __shfl_xor_sync(0xffffffffu, esum, 4);
            esum += __shfl_xor_sync(0xffffffffu, esum, 2);
            esum += __shfl_xor_sync(0xffffffffu, esum, 1);
            if (l == 0) sm[OFF_WRED + w] = esum;
        }
        __syncthreads();   // B3

        {
            int nb = b + GRID_MAIN;
            if (nb < B_) {
                if (tid < 50)
                    cp_async16(smem_u32(smi + OFF_NID + tid * 4),
                               (const int4*)(hist_id + (size_t)nb * T_) + tid);
                else if (tid == 50)
                    cp_async4(smem_u32(smi + OFF_NTGT), target + nb);
            }
            CP_COMMIT();   // P
        }

        {
            float ss = 0.f;
#pragma unroll
            for (int i = 0; i < 13; ++i) ss += sm[OFF_WRED + i];
            float inv = 1.f / ss;
            int j2 = (tid & 31) * 2, g = w;
            int tb = (g * 200) >> 4, te = ((g + 1) * 200) >> 4;
            float ax = 0.f, ay = 0.f;
            for (int t = tb; t < te; ++t) {
                float wt = sm[OFF_SC + t];
                float2 h = *(const float2*)(sm + OFF_HIST + t * PH + j2);
                ax = fmaf(wt, h.x, ax);
                ay = fmaf(wt, h.y, ay);
            }
            sm[OFF_RED + g * 64 + j2]     = ax * inv;
            sm[OFF_RED + g * 64 + j2 + 1] = ay * inv;
        }
        __syncthreads();   // B6
        if (tid < 64) {
            float iv = 0.f;
#pragma unroll
            for (int g = 0; g < 16; ++g) iv += sm[OFF_RED + g * 64 + tid];
            g_inter[b * 64 + tid] = iv;
        }
    }
}

// ============================================================
// final MLP v6: bf16x2 split tensor cores with PRE-SPLIT weights.
// 16 rows/CTA, grid 256, 2 CTAs/SM, 12-chunk double-buffered pipeline.
// ============================================================
#define DR   16
#define FPX  136   // X pitch (fp32 words)
#define P1P  264   // mw1 plane pitch (8lm+l4 conflict-free)
#define P2P  136   // mw2 plane pitch
#define PG1  132   // G1 plane pitch (4l4+lm conflict-free)
#define FX    0        // 16*136 = 2176
#define FG1H  2176     // 16*132 = 2112 -> 4288
#define FG1L  4288     // 2112 -> 6400
#define FWT0  6400     // 8448 (hi at +0, lo at +4224) -> 14848
#define FWT1  14848    // 8448 -> 23296
#define FMB1  23296    // 256
#define FMB2  23552    // 128
#define FOW   23680    // 128
#define FRED  23808    // 128
#define FTGT  23936    // 16 (int view)
#define SMEM_F_FLOATS 23952
#define SMEM_F_BYTES  (SMEM_F_FLOATS * 4)
#define LOOFF 4224     // lo-plane offset within a WT buffer

__global__ __launch_bounds__(256, 2) void din_final(
    const int* __restrict__ target,
    const float* __restrict__ table,
    const float* __restrict__ mb1, const float* __restrict__ mb2,
    const float* __restrict__ ow,  const float* __restrict__ ob,
    float* __restrict__ out) {
    extern __shared__ float sm[];
    unsigned int* smu = (unsigned int*)sm;
    int* smi = (int*)sm;
    const int tid = threadIdx.x;
    const int w   = tid >> 5;   // 0..7
    const int l   = tid & 31;
    const int l4  = l >> 2;
    const int lm  = l & 3;
    const int b0  = blockIdx.x * DR;

    if (tid < DR) smi[FTGT + tid] = target[b0 + tid];
    sm[FMB1 + tid] = mb1[tid];
    if (tid < 128) { sm[FMB2 + tid] = mb2[tid]; sm[FOW + tid] = ow[tid]; }
    __syncthreads();

    // ---- X = concat(item, interest), fp32 ----
    {
        const float4* tab4 = (const float4*)table;
        const float4* int4p = (const float4*)g_inter;
        for (int idx = tid; idx < DR * 32; idx += 256) {
            int rr = idx >> 5, v = idx & 31;
            float4 x = (v < 16)
                ? tab4[(size_t)smi[FTGT + rr] * 16 + v]
                : int4p[(size_t)(b0 + rr) * 16 + (v - 16)];
            *(float4*)(sm + FX + rr * FPX + v * 4) = x;
        }
    }

    // ---- issue chunk 0 (mw1 kpairs 0..15, hi+lo planes) into FWT0 ----
    {
        const uint4* srcH = (const uint4*)g_w1hi;
        const uint4* srcL = (const uint4*)g_w1lo;
        unsigned int* dst = smu + FWT0;
        for (int idx = tid; idx < 1024; idx += 256) {
            int r = idx >> 6, v = idx & 63;
            cp_async16(smem_u32(dst + r * P1P + v * 4), srcH + r * 64 + v);
            cp_async16(smem_u32(dst + LOOFF + r * P1P + v * 4), srcL + r * 64 + v);
        }
        CP_COMMIT();
    }

    const int n0w  = w * 32;
    const int n0w2 = w * 16;
    float acc1[16], acc2[8];

    for (int c = 0; c < 12; ++c) {
        CP_WAIT0();
        __syncthreads();   // chunk c visible; prior compute done

        // issue chunk c+1 (both planes)
        if (c < 11) {
            int nc = c + 1;
            unsigned int* dst = smu + ((nc & 1) ? FWT1 : FWT0);
            if (nc < 4) {
                const uint4* srcH = (const uint4*)g_w1hi + nc * 1024;
                const uint4* srcL = (const uint4*)g_w1lo + nc * 1024;
                for (int idx = tid; idx < 1024; idx += 256) {
                    int r = idx >> 6, v = idx & 63;
                    cp_async16(smem_u32(dst + r * P1P + v * 4), srcH + r * 64 + v);
                    cp_async16(smem_u32(dst + LOOFF + r * P1P + v * 4), srcL + r * 64 + v);
                }
            } else {
                const uint4* srcH = (const uint4*)g_w2hi + (nc - 4) * 512;
                const uint4* srcL = (const uint4*)g_w2lo + (nc - 4) * 512;
                for (int idx = tid; idx < 512; idx += 256) {
                    int r = idx >> 5, v = idx & 31;
                    cp_async16(smem_u32(dst + r * P2P + v * 4), srcH + r * 32 + v);
                    cp_async16(smem_u32(dst + LOOFF + r * P2P + v * 4), srcL + r * 32 + v);
                }
            }
            CP_COMMIT();
        }

        const unsigned int* wth = smu + ((c & 1) ? FWT1 : FWT0);
        const unsigned int* wtl = wth + LOOFF;

        if (c == 0) {
#pragma unroll
            for (int nt = 0; nt < 4; ++nt) {
                float bb0 = sm[FMB1 + n0w + nt * 8 + 2 * lm];
                float bb1 = sm[FMB1 + n0w + nt * 8 + 2 * lm + 1];
                acc1[nt * 4 + 0] = bb0; acc1[nt * 4 + 1] = bb1;
                acc1[nt * 4 + 2] = bb0; acc1[nt * 4 + 3] = bb1;
            }
        }
        if (c == 4) {
#pragma unroll
            for (int nt = 0; nt < 2; ++nt) {
                float bb0 = sm[FMB2 + n0w2 + nt * 8 + 2 * lm];
                float bb1 = sm[FMB2 + n0w2 + nt * 8 + 2 * lm + 1];
                acc2[nt * 4 + 0] = bb0; acc2[nt * 4 + 1] = bb1;
                acc2[nt * 4 + 2] = bb0; acc2[nt * 4 + 3] = bb1;
            }
        }

        if (c < 4) {
            // ---- stage 1: X k-chunk [32c..32c+32) @ mw1 chunk (bf16x2) ----
#pragma unroll
            for (int s = 0; s < 2; ++s) {
                const float* xb = sm + FX + l4 * FPX + c * 32 + s * 16 + 2 * lm;
                float2 xa = *(const float2*)(xb);
                float2 xbv = *(const float2*)(xb + 8 * FPX);
                float2 xc = *(const float2*)(xb + 8);
                float2 xd = *(const float2*)(xb + 8 * FPX + 8);
                unsigned int ah0, al0, ah1, al1, ah2, al2, ah3, al3;
                split2_bf16(xa.x,  xa.y,  ah0, al0);
                split2_bf16(xbv.x, xbv.y, ah1, al1);
                split2_bf16(xc.x,  xc.y,  ah2, al2);
                split2_bf16(xd.x,  xd.y,  ah3, al3);
#pragma unroll
                for (int nt = 0; nt < 4; ++nt) {
                    int bo = (s * 8 + lm) * P1P + n0w + nt * 8 + l4;
                    unsigned int b0h = wth[bo], b1h = wth[bo + 4 * P1P];
                    unsigned int b0l = wtl[bo], b1l = wtl[bo + 4 * P1P];
                    int base = nt * 4;
                    mma_bf16(acc1[base + 0], acc1[base + 1], acc1[base + 2], acc1[base + 3],
                             ah0, ah1, ah2, ah3, b0h, b1h);
                    mma_bf16(acc1[base + 0], acc1[base + 1], acc1[base + 2], acc1[base + 3],
                             al0, al1, al2, al3, b0h, b1h);
                    mma_bf16(acc1[base + 0], acc1[base + 1], acc1[base + 2], acc1[base + 3],
                             ah0, ah1, ah2, ah3, b0l, b1l);
                }
            }
            if (c == 3) {
                // G1 = relu(acc1) -> pre-split hi/lo planes [row][kpair]
#pragma unroll
                for (int nt = 0; nt < 4; ++nt) {
                    int base = nt * 4;
                    int kp = (n0w >> 1) + nt * 4 + lm;
                    float r0 = fmaxf(acc1[base + 0], 0.f);
                    float r1 = fmaxf(acc1[base + 1], 0.f);
                    float r2 = fmaxf(acc1[base + 2], 0.f);
                    float r3 = fmaxf(acc1[base + 3], 0.f);
                    unsigned int hw, lw;
                    split2_bf16(r0, r1, hw, lw);
                    smu[FG1H + l4 * PG1 + kp] = hw;
                    smu[FG1L + l4 * PG1 + kp] = lw;
                    split2_bf16(r2, r3, hw, lw);
                    smu[FG1H + (l4 + 8) * PG1 + kp] = hw;
                    smu[FG1L + (l4 + 8) * PG1 + kp] = lw;
                }
            }
        } else {
            // ---- stage 2: G1 k-chunk @ mw2 chunk (A pure LDS, no splits) ----
            int ck = c - 4;
#pragma unroll
            for (int s = 0; s < 2; ++s) {
                int kb = ck * 16 + s * 8 + lm;
                unsigned int ah0 = smu[FG1H + l4 * PG1 + kb];
                unsigned int ah1 = smu[FG1H + (l4 + 8) * PG1 + kb];
                unsigned int ah2 = smu[FG1H + l4 * PG1 + kb + 4];
                unsigned int ah3 = smu[FG1H + (l4 + 8) * PG1 + kb + 4];
                unsigned int al0 = smu[FG1L + l4 * PG1 + kb];
                unsigned int al1 = smu[FG1L + (l4 + 8) * PG1 + kb];
                unsigned int al2 = smu[FG1L + l4 * PG1 + kb + 4];
                unsigned int al3 = smu[FG1L + (l4 + 8) * PG1 + kb + 4];
#pragma unroll
                for (int nt = 0; nt < 2; ++nt) {
                    int bo = (s * 8 + lm) * P2P + n0w2 + nt * 8 + l4;
                    unsigned int b0h = wth[bo], b1h = wth[bo + 4 * P2P];
                    unsigned int b0l = wtl[bo], b1l = wtl[bo + 4 * P2P];
                    int base = nt * 4;
                    mma_bf16(acc2[base + 0], acc2[base + 1], acc2[base + 2], acc2[base + 3],
                             ah0, ah1, ah2, ah3, b0h, b1h);
                    mma_bf16(acc2[base + 0], acc2[base + 1], acc2[base + 2], acc2[base + 3],
                             al0, al1, al2, al3, b0h, b1h);
                    mma_bf16(acc2[base + 0], acc2[base + 1], acc2[base + 2], acc2[base + 3],
                             ah0, ah1, ah2, ah3, b0l, b1l);
                }
            }
        }
    }

    // ---- stage 3: out = relu(acc2) @ ow + ob ----
    float pA = 0.f, pB = 0.f;
#pragma unroll
    for (int nt = 0; nt < 2; ++nt) {
        int base = nt * 4;
        float w0 = sm[FOW + n0w2 + nt * 8 + 2 * lm];
        float w1 = sm[FOW + n0w2 + nt * 8 + 2 * lm + 1];
        pA = fmaf(fmaxf(acc2[base + 0], 0.f), w0,
             fmaf(fmaxf(acc2[base + 1], 0.f), w1, pA));
        pB = fmaf(fmaxf(acc2[base + 2], 0.f), w0,
             fmaf(fmaxf(acc2[base + 3], 0.f), w1, pB));
    }
    pA += __shfl_xor_sync(0xffffffffu, pA, 1);
    pA += __shfl_xor_sync(0xffffffffu, pA, 2);
    pB += __shfl_xor_sync(0xffffffffu, pB, 1);
    pB += __shfl_xor_sync(0xffffffffu, pB, 2);
    if (lm == 0) {
        sm[FRED + w * 16 + l4]     = pA;
        sm[FRED + w * 16 + l4 + 8] = pB;
    }
    __syncthreads();
    if (tid < DR) {
        float p = ob[0];
#pragma unroll
        for (int w8 = 0; w8 < 8; ++w8) p += sm[FRED + w8 * 16 + tid];
        out[b0 + tid] = p;
    }
}

// ============================================================
// launch: 4-launch pattern (p1, main, p2, final) so ncu -s5 -c1
// lands on din_main (launch #5 mod 4 == 1).
// ============================================================
extern "C" void kernel_launch(void* const* d_in, const int* in_sizes, int n_in,
                              void* d_out, int out_size) {
    const int*   target  = (const int*)d_in[0];
    const int*   hist_id = (const int*)d_in[1];
    const int*   mask    = (const int*)d_in[2];
    const float* table   = (const float*)d_in[3];
    const float* aw1     = (const float*)d_in[4];
    const float* ab1     = (const float*)d_in[5];
    const float* aw2     = (const float*)d_in[6];
    const float* ab2     = (const float*)d_in[7];
    const float* aow     = (const float*)d_in[8];
    const float* aob     = (const float*)d_in[9];
    const float* mw1     = (const float*)d_in[10];
    const float* mb1     = (const float*)d_in[11];
    const float* mw2     = (const float*)d_in[12];
    const float* mb2     = (const float*)d_in[13];
    const float* ow      = (const float*)d_in[14];
    const float* ob      = (const float*)d_in[15];
    float* out = (float*)d_out;

    cudaFuncSetAttribute(din_main, cudaFuncAttributeMaxDynamicSharedMemorySize, SMEM_B_BYTES);
    cudaFuncSetAttribute(din_final, cudaFuncAttributeMaxDynamicSharedMemorySize, SMEM_F_BYTES);

    prep_w1<<<32, 512>>>(mw1);
    din_main<<<GRID_MAIN, 512, SMEM_B_BYTES>>>(hist_id, mask, table, target, aw1,
                                               ab1, aw2, ab2, aow, aob);
    prep_w2<<<32, 512>>>(mw2);
    din_final<<<B_ / DR, 256, SMEM_F_BYTES>>>(target, table, mb1, mb2, ow, ob, out);
}

// round 16
// speedup vs baseline: 1.4701x; 1.0512x over previous
#include <cuda_runtime.h>
#include <cuda_bf16.h>
#include <math.h>
#include <stdint.h>

// Problem constants
#define B_  4096
#define T_  200
#define E_  64
#define A1_ 64
#define A2_ 32
#define M1_ 256
#define M2_ 128
#define GRID_MAIN 296   // 2 CTAs per SM x 148 SMs

// -------- device scratch (no allocations allowed) --------
__device__ float g_inter[B_ * 64];        // interest vectors
__device__ unsigned int g_w1hi[64 * 256]; // mw1 bf16-pair hi plane [kpair][n]
__device__ unsigned int g_w1lo[64 * 256]; // mw1 lo plane
__device__ unsigned int g_w2hi[128 * 128];// mw2 hi plane
__device__ unsigned int g_w2lo[128 * 128];// mw2 lo plane

// ---- bf16 helpers ----
__device__ __forceinline__ unsigned int pack_bf16(float lo, float hi) {
    unsigned int r;   // d = {hi, lo}
    asm("cvt.rn.bf16x2.f32 %0, %1, %2;" : "=r"(r) : "f"(hi), "f"(lo));
    return r;
}
__device__ __forceinline__ void split2_bf16(float x0, float x1,
                                            unsigned int& hi, unsigned int& lo) {
    hi = pack_bf16(x0, x1);
    float h0 = __bfloat162float(__float2bfloat16(x0));
    float h1 = __bfloat162float(__float2bfloat16(x1));
    lo = pack_bf16(x0 - h0, x1 - h1);
}
__device__ __forceinline__ void mma_bf16(
    float& c0, float& c1, float& c2, float& c3,
    unsigned int a0, unsigned int a1, unsigned int a2, unsigned int a3,
    unsigned int b0, unsigned int b1) {
    asm("mma.sync.aligned.m16n8k16.row.col.f32.bf16.bf16.f32 "
        "{%0,%1,%2,%3},{%4,%5,%6,%7},{%8,%9},{%0,%1,%2,%3};"
        : "+f"(c0), "+f"(c1), "+f"(c2), "+f"(c3)
        : "r"(a0), "r"(a1), "r"(a2), "r"(a3), "r"(b0), "r"(b1));
}
// ---- cp.async helpers ----
__device__ __forceinline__ void cp_async16(unsigned int dst, const void* src) {
    asm volatile("cp.async.ca.shared.global [%0], [%1], 16;" :: "r"(dst), "l"(src) : "memory");
}
__device__ __forceinline__ void cp_async4(unsigned int dst, const void* src) {
    asm volatile("cp.async.ca.shared.global [%0], [%1], 4;" :: "r"(dst), "l"(src) : "memory");
}
__device__ __forceinline__ unsigned int smem_u32(const void* p) {
    return (unsigned int)__cvta_generic_to_shared(p);
}
#define CP_COMMIT() asm volatile("cp.async.commit_group;" ::: "memory")
#define CP_WAIT0()  asm volatile("cp.async.wait_group 0;" ::: "memory")
// ---- cp.async.bulk + mbarrier helpers ----
__device__ __forceinline__ void cp_async_bulk(unsigned int dst, const void* src,
                                              unsigned int bytes, unsigned int mbar) {
    asm volatile(
        "cp.async.bulk.shared::cluster.global.mbarrier::complete_tx::bytes "
        "[%0], [%1], %2, [%3];"
        :: "r"(dst), "l"(src), "r"(bytes), "r"(mbar) : "memory");
}
__device__ __forceinline__ void mbar_init(unsigned int mbar, unsigned int count) {
    asm volatile("mbarrier.init.shared.b64 [%0], %1;" :: "r"(mbar), "r"(count) : "memory");
}
__device__ __forceinline__ void mbar_arrive_expect_tx(unsigned int mbar, unsigned int tx) {
    asm volatile("mbarrier.arrive.expect_tx.shared.b64 _, [%0], %1;"
                 :: "r"(mbar), "r"(tx) : "memory");
}
__device__ __forceinline__ void mbar_wait_parity(unsigned int mbar, unsigned int parity) {
    asm volatile(
        "{\n\t.reg .pred P1;\n\t"
        "WAIT_%=:\n\t"
        "mbarrier.try_wait.parity.acquire.cta.shared::cta.b64 P1, [%0], %1, 0x989680;\n\t"
        "@P1 bra DONE_%=;\n\t"
        "bra WAIT_%=;\n\t"
        "DONE_%=:\n\t}"
        :: "r"(mbar), "r"(parity) : "memory");
}

// ============================================================
// prep kernel: offline bf16x2 split of mw1 + mw2 into hi/lo planes
// ============================================================
__global__ void prep_w(const float* __restrict__ mw1, const float* __restrict__ mw2) {
    int idx = blockIdx.x * blockDim.x + threadIdx.x;   // 0..32767
    if (idx < 16384) {
        int p = idx >> 8, n = idx & 255;
        float x0 = mw1[(2 * p) * 256 + n];
        float x1 = mw1[(2 * p + 1) * 256 + n];
        unsigned int hi, lo;
        split2_bf16(x0, x1, hi, lo);
        g_w1hi[idx] = hi;
        g_w1lo[idx] = lo;
    } else {
        int j = idx - 16384;
        int p = j >> 7, n = j & 127;
        float x0 = mw2[(2 * p) * 128 + n];
        float x1 = mw2[(2 * p + 1) * 128 + n];
        unsigned int hi, lo;
        split2_bf16(x0, x1, hi, lo);
        g_w2hi[j] = hi;
        g_w2lo[j] = lo;
    }
}

// ============================================================
// main kernel: PERSISTENT, 296x512, 2 CTAs/SM.
// HIST gather via cp.async.bulk (200 DMA ops vs 3200 LDGSTS)
// completed through an smem mbarrier; bf16 k16 attention MLP.
// ============================================================
#define PH  68
#define PWB 36
#define OFF_HIST  0
#define OFF_WCB   14144
#define OFF_W2B   16448
#define OFF_QV    17600
#define OFF_QB    17664
#define OFF_AB2   17728
#define OFF_AOW   17760
#define OFF_SC    17792
#define OFF_MSK   18000
#define OFF_WRED  18208
#define OFF_RED   18240
#define OFF_WHPB  19264
#define OFF_WQB   23360
#define OFF_NID   25408
#define OFF_NTGT  25616
#define OFF_MBAR  25618   // 8B, 8B-aligned (25618*4 % 8 == 0)
#define SMEM_B_FLOATS 25632
#define SMEM_B_BYTES  (SMEM_B_FLOATS * 4)

__global__ __launch_bounds__(512, 2) void din_main(
    const int* __restrict__ hist_id,
    const int* __restrict__ mask,
    const float* __restrict__ table,
    const int* __restrict__ target,
    const float* __restrict__ aw1,
    const float* __restrict__ ab1,
    const float* __restrict__ aw2,
    const float* __restrict__ ab2,
    const float* __restrict__ aow,
    const float* __restrict__ aob) {
    extern __shared__ float sm[];
    unsigned int* smu = (unsigned int*)sm;
    int* smi = (int*)sm;
    unsigned int* whpb = smu + OFF_WHPB;
    __nv_bfloat16* wqb = (__nv_bfloat16*)(smu + OFF_WQB);
    const int tid = threadIdx.x;
    const int w   = tid >> 5;
    const int l   = tid & 31;
    const int l4  = l >> 2;
    const int lm  = l & 3;
    const unsigned int mbar = smem_u32(smu + OFF_MBAR);

    // ---- loop-invariant staging (once per CTA) ----
    if (tid < 32)        sm[OFF_AB2 + tid]      = ab2[tid];
    else if (tid < 64)   sm[OFF_AOW + tid - 32] = aow[tid - 32];
    for (int idx = tid; idx < 32 * 32; idx += 512) {
        int kp = idx & 31, n = idx >> 5;
        float v0 = aw2[(2 * kp) * 32 + n];
        float v1 = aw2[(2 * kp + 1) * 32 + n];
        smu[OFF_W2B + n * PWB + kp] = pack_bf16(v0, v1);
    }
    for (int idx = tid; idx < 64 * 64; idx += 512) {
        int k = idx & 63, n = idx >> 6;
        float a = aw1[k * 64 + n];
        float bb = aw1[(64 + k) * 64 + n];
        float c = aw1[(128 + k) * 64 + n];
        float d = aw1[(192 + k) * 64 + n];
        whpb[n * 64 + k] = pack_bf16(a + c, d);
        wqb[k * 64 + n] = __float2bfloat16(bb - c);
    }
    {
        float4* hist4 = (float4*)(sm + OFF_HIST);
        for (int idx = tid; idx < 8 * 17; idx += 512) {
            int t = 200 + idx / 17, v = idx % 17;
            hist4[t * 17 + v] = make_float4(0.f, 0.f, 0.f, 0.f);
        }
    }
    if (tid < 200) smi[OFF_NID + tid] = hist_id[(size_t)blockIdx.x * T_ + tid];
    if (tid == 256) smi[OFF_NTGT] = target[blockIdx.x];
    if (tid == 0) mbar_init(mbar, 200);   // one arrival per gather row
    const float aob0 = aob[0];
    const float ab1v = (tid < 64) ? ab1[tid] : 0.f;
    unsigned int ph = 0;                  // mbarrier phase parity

    for (int b = blockIdx.x; b < B_; b += GRID_MAIN) {
        CP_WAIT0();        // NID prefetch (P) landed
        __syncthreads();   // B0: NID/NTGT/mbar visible; prior iteration done

        // --- HIST gather: 200 bulk DMA ops (1 row = 256B each) ---
        if (tid < T_) {
            mbar_arrive_expect_tx(mbar, 256);
            cp_async_bulk(smem_u32(sm + OFF_HIST + tid * PH),
                          table + (size_t)smi[OFF_NID + tid] * 64, 256, mbar);
        }
        // --- group A: QV (target from smem) + MSK via cp.async ---
        if (tid < 16) {
            int tgt = smi[OFF_NTGT];
            cp_async16(smem_u32(sm + OFF_QV + tid * 4),
                       (const float4*)table + (size_t)tgt * 16 + tid);
        } else if (tid < 66) {
            cp_async16(smem_u32(smi + OFF_MSK + (tid - 16) * 4),
                       (const int4*)(mask + (size_t)b * T_) + (tid - 16));
        }
        CP_COMMIT();   // A
        CP_WAIT0();    // A done (bulk ops tracked by mbar, not groups)
        __syncthreads();   // B1: QV/MSK visible

        // --- qb partials (overlaps bulk gather) ---
        {
            int n = tid & 63, kc = tid >> 6;
            float acc = 0.f;
#pragma unroll
            for (int i = 0; i < 8; ++i) {
                int k = kc * 8 + i;
                acc = fmaf(sm[OFF_QV + k], __bfloat162float(wqb[k * 64 + n]), acc);
            }
            sm[OFF_RED + kc * 64 + n] = acc;
        }
        __syncthreads();   // B1.5
        if (tid < 64) {
            float acc = ab1v;
#pragma unroll
            for (int kc = 0; kc < 8; ++kc) acc += sm[OFF_RED + kc * 64 + tid];
            sm[OFF_QB + tid] = acc;
        }
        // --- fold Wc -> bf16 pairs (overlaps bulk gather) ---
        for (int idx = tid; idx < 64 * 32; idx += 512) {
            int kp = idx & 31, n = idx >> 5;
            uint2 hp2 = *(const uint2*)(whpb + n * 64 + 2 * kp);
            __nv_bfloat162 h0 = *(__nv_bfloat162*)&hp2.x;
            __nv_bfloat162 h1 = *(__nv_bfloat162*)&hp2.y;
            float f0 = fmaf(sm[OFF_QV + 2 * kp],     __bfloat162float(h0.y),
                            __bfloat162float(h0.x));
            float f1 = fmaf(sm[OFF_QV + 2 * kp + 1], __bfloat162float(h1.y),
                            __bfloat162float(h1.x));
            smu[OFF_WCB + n * PWB + kp] = pack_bf16(f0, f1);
        }
        __syncthreads();   // B2: QB/WCB visible

        // --- wait for bulk gather completion (acquire) ---
        mbar_wait_parity(mbar, ph);
        ph ^= 1;

        // ====== fused attention MLP (bf16 k16): warps 0..12, rows [16w,+16) ===
        if (w < 13) {
            const int mt = w;

            unsigned int a[4][4];
            {
                const float* abase = sm + OFF_HIST + (mt * 16 + l4) * PH + 2 * lm;
#pragma unroll
                for (int ks = 0; ks < 4; ++ks) {
                    float2 v00 = *(const float2*)(abase + 16 * ks);
                    float2 v10 = *(const float2*)(abase + 16 * ks + 8 * PH);
                    float2 v01 = *(const float2*)(abase + 16 * ks + 8);
                    float2 v11 = *(const float2*)(abase + 16 * ks + 8 * PH + 8);
                    a[ks][0] = pack_bf16(v00.x, v00.y);
                    a[ks][1] = pack_bf16(v10.x, v10.y);
                    a[ks][2] = pack_bf16(v01.x, v01.y);
                    a[ks][3] = pack_bf16(v11.x, v11.y);
                }
            }

            float d0[4], d1[4], d2[4], d3[4];
#pragma unroll
            for (int nt = 0; nt < 4; ++nt) {
                float bb0 = sm[OFF_AB2 + nt * 8 + 2 * lm];
                float bb1 = sm[OFF_AB2 + nt * 8 + 2 * lm + 1];
                d0[nt] = bb0; d1[nt] = bb1; d2[nt] = bb0; d3[nt] = bb1;
            }

            const unsigned int* wcbw = smu + OFF_WCB + l4 * PWB + lm;
            const unsigned int* w2bw = smu + OFF_W2B + l4 * PWB + lm;

#pragma unroll
            for (int j = 0; j < 4; ++j) {
                unsigned int A2[4];
#pragma unroll
                for (int t2 = 0; t2 < 2; ++t2) {
                    const int kk = 2 * j + t2;
                    float c0 = sm[OFF_QB + kk * 8 + 2 * lm];
                    float c1 = sm[OFF_QB + kk * 8 + 2 * lm + 1];
                    float c2 = c0, c3 = c1;
                    const unsigned int* wb = wcbw + kk * 8 * PWB;
#pragma unroll
                    for (int ks = 0; ks < 4; ++ks) {
                        unsigned int b0 = wb[8 * ks];
                        unsigned int b1 = wb[8 * ks + 4];
                        mma_bf16(c0, c1, c2, c3,
                                 a[ks][0], a[ks][1], a[ks][2], a[ks][3], b0, b1);
                    }
                    A2[2 * t2 + 0] = pack_bf16(fmaxf(c0, 0.f), fmaxf(c1, 0.f));
                    A2[2 * t2 + 1] = pack_bf16(fmaxf(c2, 0.f), fmaxf(c3, 0.f));
                }
                const unsigned int* w2 = w2bw + 8 * j;
#pragma unroll
                for (int nt = 0; nt < 4; ++nt) {
                    unsigned int b0 = w2[nt * 8 * PWB];
                    unsigned int b1 = w2[nt * 8 * PWB + 4];
                    mma_bf16(d0[nt], d1[nt], d2[nt], d3[nt],
                             A2[0], A2[1], A2[2], A2[3], b0, b1);
                }
            }

            float p01 = 0.f, p23 = 0.f;
#pragma unroll
            for (int nt = 0; nt < 4; ++nt) {
                float w0 = sm[OFF_AOW + nt * 8 + 2 * lm];
                float w1 = sm[OFF_AOW + nt * 8 + 2 * lm + 1];
                p01 = fmaf(fmaxf(d0[nt], 0.f), w0, fmaf(fmaxf(d1[nt], 0.f), w1, p01));
                p23 = fmaf(fmaxf(d2[nt], 0.f), w0, fmaf(fmaxf(d3[nt], 0.f), w1, p23));
            }
            p01 += __shfl_xor_sync(0xffffffffu, p01, 1);
            p01 += __shfl_xor_sync(0xffffffffu, p01, 2);
            p23 += __shfl_xor_sync(0xffffffffu, p23, 1);
            p23 += __shfl_xor_sync(0xffffffffu, p23, 2);
            float e01 = 0.f, e23 = 0.f;
            if (lm == 0) {
                int r0 = mt * 16 + l4;
                int r1 = r0 + 8;
                e01 = (smi[OFF_MSK + r0] != 0) ? __expf(p01 + aob0) : 0.f;
                sm[OFF_SC + r0] = e01;
                if (r1 < T_) {
                    e23 = (smi[OFF_MSK + r1] != 0) ? __expf(p23 + aob0) : 0.f;
                    sm[OFF_SC + r1] = e23;
                }
            }
            float esum = e01 + e23;
            esum += __shfl_xor_sync(0xffffffffu, esum, 16);
            esum += __shfl_xor_sync(0xffffffffu, esum, 8);
            esum += __shfl_xor_sync(0xffffffffu, esum, 4);
            esum += __shfl_xor_sync(0xffffffffu, esum, 2);
            esum += __shfl_xor_sync(0xffffffffu, esum, 1);
            if (l == 0) sm[OFF_WRED + w] = esum;
        }
        __syncthreads();   // B3: e-values + warp sums ready

        // --- prefetch next-iter IDs + target (group P) ---
        {
            int nb = b + GRID_MAIN;
            if (nb < B_) {
                if (tid < 50)
                    cp_async16(smem_u32(smi + OFF_NID + tid * 4),
                               (const int4*)(hist_id + (size_t)nb * T_) + tid);
                else if (tid == 50)
                    cp_async4(smem_u32(smi + OFF_NTGT), target + nb);
            }
            CP_COMMIT();   // P
        }

        // ---- interest (float2, 16 warp-groups; normalization folded) ----
        {
            float ss = 0.f;
#pragma unroll
            for (int i = 0; i < 13; ++i) ss += sm[OFF_WRED + i];
            float inv = 1.f / ss;
            int j2 = (tid & 31) * 2, g = w;
            int tb = (g * 200) >> 4, te = ((g + 1) * 200) >> 4;
            float ax = 0.f, ay = 0.f;
            for (int t = tb; t < te; ++t) {
                float wt = sm[OFF_SC + t];
                float2 h = *(const float2*)(sm + OFF_HIST + t * PH + j2);
                ax = fmaf(wt, h.x, ax);
                ay = fmaf(wt, h.y, ay);
            }
            sm[OFF_RED + g * 64 + j2]     = ax * inv;
            sm[OFF_RED + g * 64 + j2 + 1] = ay * inv;
        }
        __syncthreads();   // B6
        if (tid < 64) {
            float iv = 0.f;
#pragma unroll
            for (int g = 0; g < 16; ++g) iv += sm[OFF_RED + g * 64 + tid];
            g_inter[b * 64 + tid] = iv;
        }
    }
}

// ============================================================
// final MLP v6 (unchanged): bf16x2 pre-split weights, 16 rows/CTA,
// grid 256, 2 CTAs/SM, 12-chunk double-buffered pipeline.
// ============================================================
#define DR   16
#define FPX  136
#define P1P  264
#define P2P  136
#define PG1  132
#define FX    0
#define FG1H  2176
#define FG1L  4288
#define FWT0  6400
#define FWT1  14848
#define FMB1  23296
#define FMB2  23552
#define FOW   23680
#define FRED  23808
#define FTGT  23936
#define SMEM_F_FLOATS 23952
#define SMEM_F_BYTES  (SMEM_F_FLOATS * 4)
#define LOOFF 4224

__global__ __launch_bounds__(256, 2) void din_final(
    const int* __restrict__ target,
    const float* __restrict__ table,
    const float* __restrict__ mb1, const float* __restrict__ mb2,
    const float* __restrict__ ow,  const float* __restrict__ ob,
    float* __restrict__ out) {
    extern __shared__ float sm[];
    unsigned int* smu = (unsigned int*)sm;
    int* smi = (int*)sm;
    const int tid = threadIdx.x;
    const int w   = tid >> 5;
    const int l   = tid & 31;
    const int l4  = l >> 2;
    const int lm  = l & 3;
    const int b0  = blockIdx.x * DR;

    if (tid < DR) smi[FTGT + tid] = target[b0 + tid];
    sm[FMB1 + tid] = mb1[tid];
    if (tid < 128) { sm[FMB2 + tid] = mb2[tid]; sm[FOW + tid] = ow[tid]; }
    __syncthreads();

    {
        const float4* tab4 = (const float4*)table;
        const float4* int4p = (const float4*)g_inter;
        for (int idx = tid; idx < DR * 32; idx += 256) {
            int rr = idx >> 5, v = idx & 31;
            float4 x = (v < 16)
                ? tab4[(size_t)smi[FTGT + rr] * 16 + v]
                : int4p[(size_t)(b0 + rr) * 16 + (v - 16)];
            *(float4*)(sm + FX + rr * FPX + v * 4) = x;
        }
    }

    {
        const uint4* srcH = (const uint4*)g_w1hi;
        const uint4* srcL = (const uint4*)g_w1lo;
        unsigned int* dst = smu + FWT0;
        for (int idx = tid; idx < 1024; idx += 256) {
            int r = idx >> 6, v = idx & 63;
            cp_async16(smem_u32(dst + r * P1P + v * 4), srcH + r * 64 + v);
            cp_async16(smem_u32(dst + LOOFF + r * P1P + v * 4), srcL + r * 64 + v);
        }
        CP_COMMIT();
    }

    const int n0w  = w * 32;
    const int n0w2 = w * 16;
    float acc1[16], acc2[8];

    for (int c = 0; c < 12; ++c) {
        CP_WAIT0();
        __syncthreads();

        if (c < 11) {
            int nc = c + 1;
            unsigned int* dst = smu + ((nc & 1) ? FWT1 : FWT0);
            if (nc < 4) {
                const uint4* srcH = (const uint4*)g_w1hi + nc * 1024;
                const uint4* srcL = (const uint4*)g_w1lo + nc * 1024;
                for (int idx = tid; idx < 1024; idx += 256) {
                    int r = idx >> 6, v = idx & 63;
                    cp_async16(smem_u32(dst + r * P1P + v * 4), srcH + r * 64 + v);
                    cp_async16(smem_u32(dst + LOOFF + r * P1P + v * 4), srcL + r * 64 + v);
                }
            } else {
                const uint4* srcH = (const uint4*)g_w2hi + (nc - 4) * 512;
                const uint4* srcL = (const uint4*)g_w2lo + (nc - 4) * 512;
                for (int idx = tid; idx < 512; idx += 256) {
                    int r = idx >> 5, v = idx & 31;
                    cp_async16(smem_u32(dst + r * P2P + v * 4), srcH + r * 32 + v);
                    cp_async16(smem_u32(dst + LOOFF + r * P2P + v * 4), srcL + r * 32 + v);
                }
            }
            CP_COMMIT();
        }

        const unsigned int* wth = smu + ((c & 1) ? FWT1 : FWT0);
        const unsigned int* wtl = wth + LOOFF;

        if (c == 0) {
#pragma unroll
            for (int nt = 0; nt < 4; ++nt) {
                float bb0 = sm[FMB1 + n0w + nt * 8 + 2 * lm];
                float bb1 = sm[FMB1 + n0w + nt * 8 + 2 * lm + 1];
                acc1[nt * 4 + 0] = bb0; acc1[nt * 4 + 1] = bb1;
                acc1[nt * 4 + 2] = bb0; acc1[nt * 4 + 3] = bb1;
            }
        }
        if (c == 4) {
#pragma unroll
            for (int nt = 0; nt < 2; ++nt) {
                float bb0 = sm[FMB2 + n0w2 + nt * 8 + 2 * lm];
                float bb1 = sm[FMB2 + n0w2 + nt * 8 + 2 * lm + 1];
                acc2[nt * 4 + 0] = bb0; acc2[nt * 4 + 1] = bb1;
                acc2[nt * 4 + 2] = bb0; acc2[nt * 4 + 3] = bb1;
            }
        }

        if (c < 4) {
#pragma unroll
            for (int s = 0; s < 2; ++s) {
                const float* xb = sm + FX + l4 * FPX + c * 32 + s * 16 + 2 * lm;
                float2 xa = *(const float2*)(xb);
                float2 xbv = *(const float2*)(xb + 8 * FPX);
                float2 xc = *(const float2*)(xb + 8);
                float2 xd = *(const float2*)(xb + 8 * FPX + 8);
                unsigned int ah0, al0, ah1, al1, ah2, al2, ah3, al3;
                split2_bf16(xa.x,  xa.y,  ah0, al0);
                split2_bf16(xbv.x, xbv.y, ah1, al1);
                split2_bf16(xc.x,  xc.y,  ah2, al2);
                split2_bf16(xd.x,  xd.y,  ah3, al3);
#pragma unroll
                for (int nt = 0; nt < 4; ++nt) {
                    int bo = (s * 8 + lm) * P1P + n0w + nt * 8 + l4;
                    unsigned int b0h = wth[bo], b1h = wth[bo + 4 * P1P];
                    unsigned int b0l = wtl[bo], b1l = wtl[bo + 4 * P1P];
                    int base = nt * 4;
                    mma_bf16(acc1[base + 0], acc1[base + 1], acc1[base + 2], acc1[base + 3],
                             ah0, ah1, ah2, ah3, b0h, b1h);
                    mma_bf16(acc1[base + 0], acc1[base + 1], acc1[base + 2], acc1[base + 3],
                             al0, al1, al2, al3, b0h, b1h);
                    mma_bf16(acc1[base + 0], acc1[base + 1], acc1[base + 2], acc1[base + 3],
                             ah0, ah1, ah2, ah3, b0l, b1l);
                }
            }
            if (c == 3) {
#pragma unroll
                for (int nt = 0; nt < 4; ++nt) {
                    int base = nt * 4;
                    int kp = (n0w >> 1) + nt * 4 + lm;
                    float r0 = fmaxf(acc1[base + 0], 0.f);
                    float r1 = fmaxf(acc1[base + 1], 0.f);
                    float r2 = fmaxf(acc1[base + 2], 0.f);
                    float r3 = fmaxf(acc1[base + 3], 0.f);
                    unsigned int hw, lw;
                    split2_bf16(r0, r1, hw, lw);
                    smu[FG1H + l4 * PG1 + kp] = hw;
                    smu[FG1L + l4 * PG1 + kp] = lw;
                    split2_bf16(r2, r3, hw, lw);
                    smu[FG1H + (l4 + 8) * PG1 + kp] = hw;
                    smu[FG1L + (l4 + 8) * PG1 + kp] = lw;
                }
            }
        } else {
            int ck = c - 4;
#pragma unroll
            for (int s = 0; s < 2; ++s) {
                int kb = ck * 16 + s * 8 + lm;
                unsigned int ah0 = smu[FG1H + l4 * PG1 + kb];
                unsigned int ah1 = smu[FG1H + (l4 + 8) * PG1 + kb];
                unsigned int ah2 = smu[FG1H + l4 * PG1 + kb + 4];
                unsigned int ah3 = smu[FG1H + (l4 + 8) * PG1 + kb + 4];
                unsigned int al0 = smu[FG1L + l4 * PG1 + kb];
                unsigned int al1 = smu[FG1L + (l4 + 8) * PG1 + kb];
                unsigned int al2 = smu[FG1L + l4 * PG1 + kb + 4];
                unsigned int al3 = smu[FG1L + (l4 + 8) * PG1 + kb + 4];
#pragma unroll
                for (int nt = 0; nt < 2; ++nt) {
                    int bo = (s * 8 + lm) * P2P + n0w2 + nt * 8 + l4;
                    unsigned int b0h = wth[bo], b1h = wth[bo + 4 * P2P];
                    unsigned int b0l = wtl[bo], b1l = wtl[bo + 4 * P2P];
                    int base = nt * 4;
                    mma_bf16(acc2[base + 0], acc2[base + 1], acc2[base + 2], acc2[base + 3],
                             ah0, ah1, ah2, ah3, b0h, b1h);
                    mma_bf16(acc2[base + 0], acc2[base + 1], acc2[base + 2], acc2[base + 3],
                             al0, al1, al2, al3, b0h, b1h);
                    mma_bf16(acc2[base + 0], acc2[base + 1], acc2[base + 2], acc2[base + 3],
                             ah0, ah1, ah2, ah3, b0l, b1l);
                }
            }
        }
    }

    float pA = 0.f, pB = 0.f;
#pragma unroll
    for (int nt = 0; nt < 2; ++nt) {
        int base = nt * 4;
        float w0 = sm[FOW + n0w2 + nt * 8 + 2 * lm];
        float w1 = sm[FOW + n0w2 + nt * 8 + 2 * lm + 1];
        pA = fmaf(fmaxf(acc2[base + 0], 0.f), w0,
             fmaf(fmaxf(acc2[base + 1], 0.f), w1, pA));
        pB = fmaf(fmaxf(acc2[base + 2], 0.f), w0,
             fmaf(fmaxf(acc2[base + 3], 0.f), w1, pB));
    }
    pA += __shfl_xor_sync(0xffffffffu, pA, 1);
    pA += __shfl_xor_sync(0xffffffffu, pA, 2);
    pB += __shfl_xor_sync(0xffffffffu, pB, 1);
    pB += __shfl_xor_sync(0xffffffffu, pB, 2);
    if (lm == 0) {
        sm[FRED + w * 16 + l4]     = pA;
        sm[FRED + w * 16 + l4 + 8] = pB;
    }
    __syncthreads();
    if (tid < DR) {
        float p = ob[0];
#pragma unroll
        for (int w8 = 0; w8 < 8; ++w8) p += sm[FRED + w8 * 16 + tid];
        out[b0 + tid] = p;
    }
}

// ============================================================
// launch: 3-launch pattern (prep, main, final)
// ============================================================
extern "C" void kernel_launch(void* const* d_in, const int* in_sizes, int n_in,
                              void* d_out, int out_size) {
    const int*   target  = (const int*)d_in[0];
    const int*   hist_id = (const int*)d_in[1];
    const int*   mask    = (const int*)d_in[2];
    const float* table   = (const float*)d_in[3];
    const float* aw1     = (const float*)d_in[4];
    const float* ab1     = (const float*)d_in[5];
    const float* aw2     = (const float*)d_in[6];
    const float* ab2     = (const float*)d_in[7];
    const float* aow     = (const float*)d_in[8];
    const float* aob     = (const float*)d_in[9];
    const float* mw1     = (const float*)d_in[10];
    const float* mb1     = (const float*)d_in[11];
    const float* mw2     = (const float*)d_in[12];
    const float* mb2     = (const float*)d_in[13];
    const float* ow      = (const float*)d_in[14];
    const float* ob      = (const float*)d_in[15];
    float* out = (float*)d_out;

    cudaFuncSetAttribute(din_main, cudaFuncAttributeMaxDynamicSharedMemorySize, SMEM_B_BYTES);
    cudaFuncSetAttribute(din_final, cudaFuncAttributeMaxDynamicSharedMemorySize, SMEM_F_BYTES);

    prep_w<<<64, 512>>>(mw1, mw2);
    din_main<<<GRID_MAIN, 512, SMEM_B_BYTES>>>(hist_id, mask, table, target, aw1,
                                               ab1, aw2, ab2, aow, aob);
    din_final<<<B_ / DR, 256, SMEM_F_BYTES>>>(target, table, mb1, mb2, ow, ob, out);
}